// round 14
// baseline (speedup 1.0000x reference)
#include <cuda_runtime.h>
#include <math.h>
#include <stdint.h>

#define NB 16
#define NV 1024
#define ND 16
#define NE 64
#define NF 16
#define NH 128
#define NHD 64
#define BIGF 1e9f
#define VD (NV*ND)
#define ROWS_TOTAL (NB*VD)
#define NNODES (NB*NV)

// ---- scratch ------------------------------------------------------------------
__device__ float g_nodeenc[NNODES*NH];
__device__ float g_xnode[NNODES*NH];
__device__ float g_tnode[NNODES*NH];
__device__ float g_lnode[NNODES];
__device__ float g_hn1[NNODES*NH];
__device__ float g_hn2[NNODES*NH];
__device__ float g_gx[NNODES*3*NH];
__device__ float g_gh[NNODES*3*NH];
__device__ float g_uwn[NNODES*NH];
__device__ float g_wcomb[NH*NH];
__device__ float g_tpad0[NH];
__device__ float g_lpad0[1];
__device__ float g_tpad[NH];
__device__ float g_lpad[1];
__device__ float g_h2pad[NH];
__device__ float g_uwpad[NH];
__device__ float g_nw[ROWS_TOTAL];
__device__ float g_dualvars[NNODES];

// ---- host-side stream/events ----------------------------------------------------
static cudaStream_t g_sB;
static cudaEvent_t  g_ev[8];
namespace {
struct StreamInit {
    StreamInit() {
        cudaStreamCreateWithFlags(&g_sB, cudaStreamNonBlocking);
        for (int i = 0; i < 8; i++)
            cudaEventCreateWithFlags(&g_ev[i], cudaEventDisableTiming);
    }
};
static StreamInit s_streamInit;
}

__device__ __forceinline__ float sigmoidf_(float x) { return 1.f/(1.f+expf(-x)); }

// ---- bf16x2-split mma helpers ---------------------------------------------------
__device__ __forceinline__ void splitbf(float2 v, uint32_t &h, uint32_t &l) {
    asm("cvt.rn.bf16x2.f32 %0, %1, %2;" : "=r"(h) : "f"(v.y), "f"(v.x));
    float hx = __uint_as_float(h << 16);
    float hy = __uint_as_float(h & 0xffff0000u);
    asm("cvt.rn.bf16x2.f32 %0, %1, %2;" : "=r"(l) : "f"(v.y - hy), "f"(v.x - hx));
}
__device__ __forceinline__ void mma_bf16(float (&c)[4],
                                         uint32_t a0, uint32_t a1, uint32_t a2, uint32_t a3,
                                         uint32_t b0, uint32_t b1) {
    asm volatile("mma.sync.aligned.m16n8k16.row.col.f32.bf16.bf16.f32 "
                 "{%0,%1,%2,%3},{%4,%5,%6,%7},{%8,%9},{%0,%1,%2,%3};"
                 : "+f"(c[0]), "+f"(c[1]), "+f"(c[2]), "+f"(c[3])
                 : "r"(a0), "r"(a1), "r"(a2), "r"(a3), "r"(b0), "r"(b1));
}

// smem (uint32 units):
//   A hi/lo: [32 rows][68]  (row-major k-pairs, stride 68)
//   B hi/lo: [64 kp][136]   (k-major, stride 136)
#define AH_OFF 0
#define AL_OFF (32*68)
#define BH_OFF (2*32*68)
#define BL_OFF (2*32*68 + 64*136)
#define RED_OFF (2*32*68 + 2*64*136)
#define TMM_SMEM ((2*32*68 + 2*64*136 + 128)*4)

// stage A tile (32 rows x 128 k) as packed bf16x2 hi/lo, [r][kp] stride 68
__device__ __forceinline__ void stageA(uint32_t* sm_u, const float* __restrict__ A,
                                       int r0, int tid) {
    for (int i = tid; i < 32*64; i += 256) {
        int r = i >> 6, p = i & 63;
        float2 v = *(const float2*)(A + (size_t)(r0+r)*128 + p*2);
        uint32_t h, l; splitbf(v, h, l);
        sm_u[AH_OFF + r*68 + p] = h;
        sm_u[AL_OFF + r*68 + p] = l;
    }
}
// stage B tile: W row-major [k][n] (stride ws) -> smem [kp][n] stride 136
__device__ __forceinline__ void stageB(uint32_t* sm_u, const float* __restrict__ W,
                                       int colBase, int ws, int tid) {
    for (int i = tid; i < 64*128; i += 256) {
        int n = i & 127, kp = i >> 7;
        float2 v = make_float2(W[(2*kp)*ws + colBase + n], W[(2*kp+1)*ws + colBase + n]);
        uint32_t h, l; splitbf(v, h, l);
        sm_u[BH_OFF + kp*136 + n] = h;
        sm_u[BL_OFF + kp*136 + n] = l;
    }
}

// GEMM mainloop on pre-split tiles: warp tile 16m x 32n, pure LDS + MMA
__device__ __forceinline__ void tmm_core(const uint32_t* __restrict__ sm_u,
                                         float (&c)[4][4],
                                         int wm, int wn, int g, int t4) {
#pragma unroll
    for (int ks = 0; ks < 8; ks++) {
        const int ka = ks*8 + t4;
        const int rb = wm*16 + g;
        uint32_t ah[4], al[4];
        ah[0] = sm_u[AH_OFF + rb*68 + ka];
        ah[1] = sm_u[AH_OFF + (rb+8)*68 + ka];
        ah[2] = sm_u[AH_OFF + rb*68 + ka + 4];
        ah[3] = sm_u[AH_OFF + (rb+8)*68 + ka + 4];
        al[0] = sm_u[AL_OFF + rb*68 + ka];
        al[1] = sm_u[AL_OFF + (rb+8)*68 + ka];
        al[2] = sm_u[AL_OFF + rb*68 + ka + 4];
        al[3] = sm_u[AL_OFF + (rb+8)*68 + ka + 4];
        uint32_t bh[4][2], bl[4][2];
#pragma unroll
        for (int nt = 0; nt < 4; nt++) {
            int cb = wn*32 + nt*8 + g;
            bh[nt][0] = sm_u[BH_OFF + ka*136 + cb];
            bh[nt][1] = sm_u[BH_OFF + (ka+4)*136 + cb];
            bl[nt][0] = sm_u[BL_OFF + ka*136 + cb];
            bl[nt][1] = sm_u[BL_OFF + (ka+4)*136 + cb];
        }
#pragma unroll
        for (int nt = 0; nt < 4; nt++) {
            mma_bf16(c[nt], ah[0],ah[1],ah[2],ah[3], bh[nt][0],bh[nt][1]);
            mma_bf16(c[nt], ah[0],ah[1],ah[2],ah[3], bl[nt][0],bl[nt][1]);
            mma_bf16(c[nt], al[0],al[1],al[2],al[3], bh[nt][0],bh[nt][1]);
        }
    }
}

// ================= k_tnode: tnode/lnode GEMM (grid NNODES/32) ====================
extern "C" __global__ void __launch_bounds__(256,2)
k_tnode(const float* __restrict__ Wgat, const float* __restrict__ b_gat,
        const float* __restrict__ a_gat, int asel) {
    extern __shared__ uint32_t sm_u[];
    float* red = (float*)(sm_u + RED_OFF);
    const float* A = asel ? g_hn1 : g_nodeenc;
    const int r0 = blockIdx.x * 32;
    const int tid = threadIdx.x;

    stageA(sm_u, A, r0, tid);
    stageB(sm_u, Wgat, 0, 128, tid);
    __syncthreads();

    const int warp = tid >> 5, lane = tid & 31;
    const int wm = warp & 1, wn = warp >> 1;
    const int g = lane >> 2, t4 = lane & 3;

    float c[4][4];
#pragma unroll
    for (int nt = 0; nt < 4; nt++) {
        int col = wn*32 + nt*8 + 2*t4;
        c[nt][0] = b_gat[col];  c[nt][1] = b_gat[col+1];
        c[nt][2] = b_gat[col];  c[nt][3] = b_gat[col+1];
    }
    tmm_core(sm_u, c, wm, wn, g, t4);

    {
        int rA = wm*16 + g;
        float lsA = 0.f, lsB = 0.f;
#pragma unroll
        for (int nt = 0; nt < 4; nt++) {
            int col = wn*32 + nt*8 + 2*t4;
            float t0 = tanhf(c[nt][0]);
            float t1 = tanhf(c[nt][1]);
            float t2 = tanhf(c[nt][2]);
            float t3 = tanhf(c[nt][3]);
            *(float2*)(g_tnode + (size_t)(r0+rA  )*128 + col) = make_float2(t0,t1);
            *(float2*)(g_tnode + (size_t)(r0+rA+8)*128 + col) = make_float2(t2,t3);
            float a0v = a_gat[col], a1v = a_gat[col+1];
            lsA += t0*a0v + t1*a1v;
            lsB += t2*a0v + t3*a1v;
        }
#pragma unroll
        for (int o = 1; o < 4; o <<= 1) {
            lsA += __shfl_xor_sync(0xffffffff, lsA, o);
            lsB += __shfl_xor_sync(0xffffffff, lsB, o);
        }
        if (t4 == 0) {
            red[rA*4 + wn]     = lsA;
            red[(rA+8)*4 + wn] = lsB;
        }
    }
    __syncthreads();
    if (tid < 32) {
        float l = red[tid*4] + red[tid*4+1] + red[tid*4+2] + red[tid*4+3];
        g_lnode[r0 + tid] = l;
    }
}

// ================= k_gh: gh chunks (grid (NNODES/32, 3)) =========================
extern "C" __global__ void __launch_bounds__(256,2)
k_gh(const float* __restrict__ Wh, int asel) {
    extern __shared__ uint32_t sm_u[];
    const float* A = asel ? g_hn1 : g_nodeenc;
    const int y  = blockIdx.y;
    const int r0 = blockIdx.x * 32;
    const int tid = threadIdx.x;

    stageA(sm_u, A, r0, tid);
    stageB(sm_u, Wh, y*128, 384, tid);
    __syncthreads();

    const int warp = tid >> 5, lane = tid & 31;
    const int wm = warp & 1, wn = warp >> 1;
    const int g = lane >> 2, t4 = lane & 3;

    float c[4][4];
#pragma unroll
    for (int nt = 0; nt < 4; nt++)
        c[nt][0]=c[nt][1]=c[nt][2]=c[nt][3]=0.f;
    tmm_core(sm_u, c, wm, wn, g, t4);

    int rA = r0 + wm*16 + g;
#pragma unroll
    for (int nt = 0; nt < 4; nt++) {
        int col = y*128 + wn*32 + nt*8 + 2*t4;
        *(float2*)(g_gh + (size_t)rA*384 + col)     = make_float2(c[nt][0], c[nt][1]);
        *(float2*)(g_gh + (size_t)(rA+8)*384 + col) = make_float2(c[nt][2], c[nt][3]);
    }
}

// ================= k_tmm: osel 0 = gx (grid x3), osel 3 = udec (grid x1) =========
extern "C" __global__ void __launch_bounds__(256,2)
k_tmm(const float* __restrict__ Wg, int asel, int osel) {
    extern __shared__ uint32_t sm_u[];
    const float* A = (asel==2) ? g_xnode : g_hn2;
    const float* W = (osel==3) ? g_wcomb : Wg;
    const int wstride = (osel==3) ? 128 : 384;
    const int colBase = blockIdx.y * 128;
    const int r0 = blockIdx.x * 32;
    const int tid = threadIdx.x;

    stageA(sm_u, A, r0, tid);
    stageB(sm_u, W, colBase, wstride, tid);
    __syncthreads();

    const int warp = tid >> 5, lane = tid & 31;
    const int wm = warp & 1, wn = warp >> 1;
    const int g = lane >> 2, t4 = lane & 3;

    float c[4][4];
#pragma unroll
    for (int nt = 0; nt < 4; nt++)
        c[nt][0]=c[nt][1]=c[nt][2]=c[nt][3]=0.f;
    tmm_core(sm_u, c, wm, wn, g, t4);

    float* out = (osel==0) ? g_gx : g_uwn;
    const int ostride = (osel==0) ? 384 : 128;
    int rA = r0 + wm*16 + g;
#pragma unroll
    for (int nt = 0; nt < 4; nt++) {
        int col = colBase + wn*32 + nt*8 + 2*t4;
        *(float2*)(out + (size_t)rA*ostride + col)     = make_float2(c[nt][0], c[nt][1]);
        *(float2*)(out + (size_t)(rA+8)*ostride + col) = make_float2(c[nt][2], c[nt][3]);
    }
}

// ================= encoding: one block per v, 16 batches, W_enc in smem =========
extern "C" __global__ void __launch_bounds__(128)
k_nodeencF(const float* __restrict__ emb,
           const float* __restrict__ nf,
           const float* __restrict__ W_enc,
           const float* __restrict__ b_enc) {
    const int v = blockIdx.x, t = threadIdx.x;
    __shared__ float Ws[(NE+NF)*NH];
    __shared__ float e_s[NE];
    __shared__ float red[128];
    for (int i = t; i < (NE+NF)*NH; i += 128) Ws[i] = W_enc[i];
    if (t < NE) e_s[t] = emb[v*NE + t];
    __syncthreads();
    red[t] = (t < NE) ? e_s[t]*e_s[t] : 0.f;
    __syncthreads();
    for (int s = 64; s > 0; s >>= 1) { if (t < s) red[t] += red[t+s]; __syncthreads(); }
    float inv = 1.f / fmaxf(sqrtf(red[0]), 1.f);
    float base = b_enc[t];
#pragma unroll 8
    for (int k = 0; k < NE; k++) base += e_s[k]*inv*Ws[k*NH + t];
#pragma unroll
    for (int b = 0; b < NB; b++) {
        const float* nfr = nf + (size_t)(b*NV + v)*NF;
        float acc = base;
#pragma unroll
        for (int k = 0; k < NF; k++) acc += nfr[k]*Ws[(NE+k)*NH + t];
        g_nodeenc[(size_t)(b*NV + v)*NH + t] = acc;
    }
}

// ================= wprep + pads fused ============================================
extern "C" __global__ void k_pads(const float* __restrict__ bg,
                                  const float* __restrict__ Wh,
                                  const float* __restrict__ W_gat,
                                  const float* __restrict__ b_gat,
                                  const float* __restrict__ a_gat,
                                  const float* __restrict__ W1) {
    int t = threadIdx.x;  // 512
    __shared__ float h1p[128], ghp[384], red[128], h2ps[128];
    for (int i = t; i < 16384; i += 512) {
        int k = i >> 7, c = i & 127;
        float v;
        if (c < 64) v = W1[k*64 + c] + W1[(128+k)*64 + c];
        else        v = W1[(128+k)*64 + (c-64)];
        g_wcomb[i] = v;
    }
    if (t < 128) h1p[t] = (1.f - sigmoidf_(bg[t])) * tanhf(bg[256+t]);
    __syncthreads();
    if (t < 384) {
        float s = 0.f;
#pragma unroll 8
        for (int k = 0; k < 128; k++) s += h1p[k]*Wh[k*384 + t];
        ghp[t] = s;
    } else {
        int c = t - 384;
        float s = b_gat[c];
#pragma unroll 8
        for (int k = 0; k < 128; k++) s += h1p[k]*W_gat[k*128 + c];
        float t2 = tanhf(s);
        g_tpad[c] = t2;
        red[c] = t2*a_gat[c];
    }
    __syncthreads();
    for (int st = 64; st > 0; st >>= 1) { if (t < st) red[t] += red[t+st]; __syncthreads(); }
    if (t == 0) g_lpad[0] = red[0];
    if (t < 128) {
        float z = sigmoidf_(bg[t] + ghp[t]);
        float r = sigmoidf_(bg[128+t] + ghp[128+t]);
        float cand = tanhf(bg[256+t] + r*ghp[256+t]);
        float h2p = z*h1p[t] + (1.f - z)*cand;
        g_h2pad[t] = h2p;
        h2ps[t] = h2p;
        float tb = tanhf(b_gat[t]);
        g_tpad0[t] = tb;
        red[t] = tb*a_gat[t];
    }
    __syncthreads();
    for (int st = 64; st > 0; st >>= 1) { if (t < st) red[t] += red[t+st]; __syncthreads(); }
    if (t == 0) g_lpad0[0] = red[0];
    if (t < 128) {
        float u = 0.f;
#pragma unroll 8
        for (int k = 0; k < 128; k++) u += h2ps[k]*g_wcomb[k*128 + t];
        g_uwpad[t] = u;
    }
}

// ================= warp-per-node attention + x ==================================
extern "C" __global__ void k_attn(const int* __restrict__ adj,
                                  const int* __restrict__ num_nodes, int layer) {
    const int tid = threadIdx.x;
    const int lane = tid & 31;
    const int n = blockIdx.x*8 + (tid >> 5);
    const int b = n >> 10;
    const int nn = num_nodes[b];
    const float* tpad = layer ? g_tpad : g_tpad0;
    const float lpadv = (layer ? g_lpad[0] : g_lpad0[0]) - BIGF;

    int adjs = 0; float val = 0.f; float lg = -1e30f;
    if (lane < 16) {
        int a = adj[n*16 + lane];
        val = (a == nn) ? 0.f : 1.f;
        adjs = b*NV + min(a, NV-1);
        lg = (val != 0.f) ? g_lnode[adjs] : lpadv;
    }
    float mx = lg;
#pragma unroll
    for (int o = 16; o; o >>= 1) mx = fmaxf(mx, __shfl_xor_sync(0xffffffffu, mx, o));
    float e = (lane < 16) ? expf(lg - mx) : 0.f;
    float ssum = e;
#pragma unroll
    for (int o = 16; o; o >>= 1) ssum += __shfl_xor_sync(0xffffffffu, ssum, o);
    float at = e / ssum;

    float4 tp4 = *(const float4*)(tpad + lane*4);
    float4 msg = make_float4(0.f, 0.f, 0.f, 0.f);
#pragma unroll
    for (int d = 0; d < 16; d++) {
        float atd = __shfl_sync(0xffffffffu, at, d);
        int   rwd = __shfl_sync(0xffffffffu, adjs, d);
        float vdd = __shfl_sync(0xffffffffu, val, d);
        float4 tv = (vdd != 0.f) ? *(const float4*)(g_tnode + (size_t)rwd*128 + lane*4) : tp4;
        msg.x += atd*tv.x; msg.y += atd*tv.y; msg.z += atd*tv.z; msg.w += atd*tv.w;
    }
    float4 ne = *(const float4*)(g_nodeenc + (size_t)n*128 + lane*4);
    float4 o;
    o.x = tanhf(msg.x + ne.x);
    o.y = tanhf(msg.y + ne.y);
    o.z = tanhf(msg.z + ne.z);
    o.w = tanhf(msg.w + ne.w);
    *(float4*)(g_xnode + (size_t)n*128 + lane*4) = o;
}

// ================= node-level GRU combine ========================================
extern "C" __global__ void k_combnode(const float* __restrict__ bg, int mode) {
    int n   = blockIdx.x*2 + (threadIdx.x >> 7);
    int c   = threadIdx.x & 127;
    const float* hprev = mode ? g_hn1 : g_nodeenc;
    float* out         = mode ? g_hn2 : g_hn1;
    size_t i = (size_t)n*384;
    float gxz = g_gx[i + c],       ghz = g_gh[i + c];
    float gxr = g_gx[i + 128 + c], ghr = g_gh[i + 128 + c];
    float gxc = g_gx[i + 256 + c], ghc = g_gh[i + 256 + c];
    float hp  = hprev[(size_t)n*128 + c];
    float z = sigmoidf_(gxz + ghz + bg[c]);
    float r = sigmoidf_(gxr + ghr + bg[128 + c]);
    float cand = tanhf(gxc + bg[256 + c] + r*ghc);
    out[(size_t)n*128 + c] = z*hp + (1.f - z)*cand;
}

// ================= per-edge nw (float2) ==========================================
extern "C" __global__ void k_nw(const float* __restrict__ b1,
                                const float* __restrict__ W2,
                                const float* __restrict__ b2,
                                const int* __restrict__ adj,
                                const int* __restrict__ num_nodes) {
    int e = blockIdx.x*8 + (threadIdx.x >> 5);
    int lane = threadIdx.x & 31;
    int b = e / VD;
    int d = e & 15;
    int nn = num_nodes[b];
    int a_raw = adj[e];
    int an = min(a_raw, NV-1);
    bool ve = (a_raw != nn);
    int a2_raw = adj[(b*NV + an)*ND + (d ^ 1)];
    int an2 = min(a2_raw, NV-1);
    bool ve2 = (a2_raw != nn);
    const float* rowA = ve  ? (g_uwn + (size_t)(b*NV + an)*NH)        : g_uwpad;
    const float* rowB = ve2 ? (g_uwn + (size_t)(b*NV + an2)*NH + 64)  : (g_uwpad + 64);
    float2 a2 = *(const float2*)(rowA + lane*2);
    float2 c2 = *(const float2*)(rowB + lane*2);
    float2 b12 = *(const float2*)(b1 + lane*2);
    float2 w22 = *(const float2*)(W2 + lane*2);
    float s = tanhf(a2.x + c2.x + b12.x)*w22.x + tanhf(a2.y + c2.y + b12.y)*w22.y;
#pragma unroll
    for (int o = 16; o > 0; o >>= 1) s += __shfl_down_sync(0xffffffff, s, o);
    if (lane == 0) g_nw[e] = s + b2[0];
}

// ================= dual vars (split-K matvec) ====================================
extern "C" __global__ void k_dualvars(const float* __restrict__ W1,
                                      const float* __restrict__ b1,
                                      const float* __restrict__ W2,
                                      const float* __restrict__ b2,
                                      const int* __restrict__ adj,
                                      const int* __restrict__ num_nodes) {
    int bv = blockIdx.x, t = threadIdx.x;  // 128 threads
    int b = bv >> 10;
    __shared__ float ns[128];
    __shared__ float part[128];
    __shared__ float hid[64];
    __shared__ int adjs[16];
    __shared__ float vals[16];
    if (t < 16) {
        int a = adj[bv*16 + t];
        vals[t] = (a == num_nodes[b]) ? 0.f : 1.f;
        adjs[t] = b*NV + min(a, NV-1);
    }
    __syncthreads();
    float hpad = g_h2pad[t];
    float s = 0.f;
#pragma unroll
    for (int d = 0; d < 16; d++)
        s += (vals[d] != 0.f) ? g_hn2[(size_t)adjs[d]*128 + t] : hpad;
    ns[t] = s;
    __syncthreads();
    {
        int j = t & 63;
        int k0 = (t >> 6)*64;
        float a = 0.f;
#pragma unroll 8
        for (int k = 0; k < 64; k++) a += ns[k0+k]*W1[(k0+k)*NHD + j];
        part[t] = a;
    }
    __syncthreads();
    if (t < 64) hid[t] = tanhf(part[t] + part[t+64] + b1[t]) * W2[t];
    __syncthreads();
    for (int st = 32; st > 0; st >>= 1) { if (t < st) hid[t] += hid[t+st]; __syncthreads(); }
    if (t == 0) g_dualvars[bv] = fmaxf(hid[0] + b2[0], 0.f);
}

// ================= fused tail: dest softmax + sparsemax + flow + dual + out ======
#define TAILSM ((3*VD + 1024)*4)
extern "C" __global__ void __launch_bounds__(1024,1)
k_tail(const float* __restrict__ demands, const int* __restrict__ inv_adj,
       const int* __restrict__ adj, const int* __restrict__ num_nodes,
       float* __restrict__ out) {
    extern __shared__ float sm[];
    float* dest_s = sm;
    float* f0  = sm + VD;
    float* f1  = sm + 2*VD;
    float* red = sm + 3*VD;
    const int b = blockIdx.x, v = threadIdx.x;
    const int nn = num_nodes[b];
    const int base = (b*NV + v)*ND;
    const float dem = demands[b*NV + v];

    int ia[16];
    {
        float w[16]; float mx = -1e30f;
#pragma unroll
        for (int d = 0; d < 16; d++) {
            int iar = inv_adj[base + d];
            float m = (iar == nn) ? 1.f : 0.f;
            ia[d] = min(iar, NV-1);
            float val = g_nw[(b*NV + ia[d])*ND + d] - BIGF*m;
            w[d] = val; mx = fmaxf(mx, val);
        }
        float ssum = 0.f;
#pragma unroll
        for (int d = 0; d < 16; d++) { w[d] = expf(w[d]-mx); ssum += w[d]; }
        float inv = 1.f/ssum;
#pragma unroll
        for (int d = 0; d < 16; d++) dest_s[d*NV + v] = w[d]*inv;
    }
    __syncthreads();

    float nrm[16];
    {
        float z[16], valid[16];
#pragma unroll
        for (int d = 0; d < 16; d++) {
            int a = adj[base + d];
            float m = (a == nn) ? 1.f : 0.f;
            valid[d] = 1.f - m;
            z[d] = dest_s[d*NV + min(a, NV-1)] - BIGF*m;
        }
        float zs[16];
        for (int d = 0; d < 16; d++) zs[d] = z[d];
        for (int i = 1; i < 16; i++) {
            float key = zs[i]; int j = i-1;
            while (j >= 0 && zs[j] < key) { zs[j+1] = zs[j]; j--; }
            zs[j+1] = key;
        }
        float csum = 0.f, zck = 0.f; int kz = 1;
        for (int k = 1; k <= 16; k++) {
            csum += zs[k-1];
            if (1.f + (float)k*zs[k-1] > csum) { kz = k; zck = csum; }
        }
        float tau = (zck - 1.f)/(float)kz;
#pragma unroll
        for (int d = 0; d < 16; d++)
            nrm[d] = fmaxf(z[d] - tau, 0.f) * valid[d];
    }

#pragma unroll
    for (int d = 0; d < 16; d++) f0[d*NV + v] = 0.f;
    __syncthreads();
    float* cur = f0; float* nxt = f1;
    for (int it = 0; it < 10; it++) {
        float inflow = 0.f;
#pragma unroll
        for (int d = 0; d < 16; d++) inflow += cur[d*NV + ia[d]];
        float val = fmaxf(inflow - dem, 0.f);
#pragma unroll
        for (int d = 0; d < 16; d++) nxt[d*NV + v] = nrm[d]*val;
        __syncthreads();
        float* tmp = cur; cur = nxt; nxt = tmp;
    }
    float c = 0.f;
#pragma unroll
    for (int d = 0; d < 16; d++) { float f = cur[d*NV + v]; c += f*f; }

    float dvv = g_dualvars[b*NV + v];
    float ddem = dvv*dem;
    float ec = 0.f;
#pragma unroll
    for (int d = 0; d < 16; d++) {
        int a = adj[base + d];
        float m = (a == nn) ? 1.f : 0.f;
        float valid = 1.f - m;
        float dual = m*dvv;
        float dtr = g_dualvars[b*NV + min(a, NV-1)]*valid;
        float dd = dtr - dual;
        float f = 0.f, vel = 0.f;
#pragma unroll
        for (int it = 0; it < 10; it++) {
            float grad = 2.f*f + dd;
            vel = 0.9f*vel - 0.01f*grad;
            f = fmaxf(f + vel, 0.f);
        }
        float df = f*valid;
        ec += df*df + dd*df;
    }
    red[v] = c - ec + ddem;
    __syncthreads();
    for (int s = 512; s > 0; s >>= 1) { if (v < s) red[v] += red[v+s]; __syncthreads(); }
    if (v == 0) out[b] = red[0];
}

extern "C" void kernel_launch(void* const* d_in, const int* in_sizes, int n_in,
                              void* d_out, int out_size) {
    const float* demands       = (const float*)d_in[0];
    const float* node_features = (const float*)d_in[1];
    const float* node_emb      = (const float*)d_in[4];
    const float* W_enc   = (const float*)d_in[5];
    const float* b_enc   = (const float*)d_in[6];
    const float* W_gat   = (const float*)d_in[7];
    const float* b_gat   = (const float*)d_in[8];
    const float* a_gat   = (const float*)d_in[9];
    const float* W_gru_x = (const float*)d_in[10];
    const float* W_gru_h = (const float*)d_in[11];
    const float* b_gru   = (const float*)d_in[12];
    const float* W_dec1  = (const float*)d_in[13];
    const float* b_dec1  = (const float*)d_in[14];
    const float* W_dec2  = (const float*)d_in[15];
    const float* b_dec2  = (const float*)d_in[16];
    const float* W_dual1 = (const float*)d_in[17];
    const float* b_dual1 = (const float*)d_in[18];
    const float* W_dual2 = (const float*)d_in[19];
    const float* b_dual2 = (const float*)d_in[20];
    const int* adj       = (const int*)d_in[21];
    const int* inv_adj   = (const int*)d_in[22];
    const int* num_nodes = (const int*)d_in[26];
    float* out = (float*)d_out;

    cudaFuncSetAttribute(k_tnode, cudaFuncAttributeMaxDynamicSharedMemorySize, TMM_SMEM);
    cudaFuncSetAttribute(k_gh,    cudaFuncAttributeMaxDynamicSharedMemorySize, TMM_SMEM);
    cudaFuncSetAttribute(k_tmm,   cudaFuncAttributeMaxDynamicSharedMemorySize, TMM_SMEM);
    cudaFuncSetAttribute(k_tail,  cudaFuncAttributeMaxDynamicSharedMemorySize, TAILSM);

    dim3 g3(NNODES/32, 3);
    dim3 g1(NNODES/32, 1);

    // fork side stream off the (capturing) main stream
    cudaEventRecord(g_ev[0], 0);
    cudaStreamWaitEvent(g_sB, g_ev[0], 0);

    // main: node encoding ; side: pads
    k_nodeencF<<<NV, 128>>>(node_emb, node_features, W_enc, b_enc);
    cudaEventRecord(g_ev[1], 0);                                     // nodeenc ready
    k_pads<<<1, 512, 0, g_sB>>>(b_gru, W_gru_h, W_gat, b_gat, a_gat, W_dec1);
    cudaEventRecord(g_ev[2], g_sB);                                  // pads ready

    // ---- layer 1 ----
    cudaStreamWaitEvent(g_sB, g_ev[1], 0);
    k_gh<<<g3, 256, TMM_SMEM, g_sB>>>(W_gru_h, 0);                   // side: gh1
    cudaEventRecord(g_ev[3], g_sB);

    k_tnode<<<NNODES/32, 256, TMM_SMEM>>>(W_gat, b_gat, a_gat, 0);   // main: tnode1
    cudaStreamWaitEvent(0, g_ev[2], 0);                              // pads needed by attn
    k_attn<<<NNODES/8, 256>>>(adj, num_nodes, 0);
    k_tmm<<<g3, 256, TMM_SMEM>>>(W_gru_x, 2, 0);                     // gx1
    cudaStreamWaitEvent(0, g_ev[3], 0);                              // gh1 needed
    k_combnode<<<NNODES/2, 256>>>(b_gru, 0);                         // -> H1
    cudaEventRecord(g_ev[4], 0);                                     // H1 ready

    // ---- layer 2 ----
    cudaStreamWaitEvent(g_sB, g_ev[4], 0);
    k_gh<<<g3, 256, TMM_SMEM, g_sB>>>(W_gru_h, 1);                   // side: gh2
    cudaEventRecord(g_ev[5], g_sB);

    k_tnode<<<NNODES/32, 256, TMM_SMEM>>>(W_gat, b_gat, a_gat, 1);   // main: tnode2
    k_attn<<<NNODES/8, 256>>>(adj, num_nodes, 1);
    k_tmm<<<g3, 256, TMM_SMEM>>>(W_gru_x, 2, 0);                     // gx2
    cudaStreamWaitEvent(0, g_ev[5], 0);                              // gh2 needed
    k_combnode<<<NNODES/2, 256>>>(b_gru, 1);                         // -> H2
    cudaEventRecord(g_ev[6], 0);                                     // H2 ready

    // ---- tail: dualvars on side stream, decoder chain on main ----
    cudaStreamWaitEvent(g_sB, g_ev[6], 0);
    k_dualvars<<<NNODES, 128, 0, g_sB>>>(W_dual1, b_dual1, W_dual2, b_dual2, adj, num_nodes);
    cudaEventRecord(g_ev[7], g_sB);

    k_tmm<<<g1, 256, TMM_SMEM>>>(nullptr, 3, 3);                     // uwn = H2 @ wcomb
    k_nw<<<ROWS_TOTAL/8, 256>>>(b_dec1, W_dec2, b_dec2, adj, num_nodes);
    cudaStreamWaitEvent(0, g_ev[7], 0);                              // dualvars needed
    k_tail<<<NB, 1024, TAILSM>>>(demands, inv_adj, adj, num_nodes, out);
}

// round 15
// speedup vs baseline: 1.1016x; 1.1016x over previous
#include <cuda_runtime.h>
#include <math.h>
#include <stdint.h>

#define NB 16
#define NV 1024
#define ND 16
#define NE 64
#define NF 16
#define NH 128
#define NHD 64
#define BIGF 1e9f
#define VD (NV*ND)
#define ROWS_TOTAL (NB*VD)
#define NNODES (NB*NV)

// ---- scratch ------------------------------------------------------------------
__device__ float g_nodeenc[NNODES*NH];
__device__ float g_xnode[NNODES*NH];
__device__ float g_tnode[NNODES*NH];
__device__ float g_lnode[NNODES];
__device__ float g_hn1[NNODES*NH];
__device__ float g_hn2[NNODES*NH];
__device__ float g_gx[NNODES*3*NH];
__device__ float g_gh[NNODES*3*NH];
__device__ float g_uwn[NNODES*NH];
__device__ float g_wcomb[NH*NH];
__device__ float g_tpad0[NH];
__device__ float g_lpad0[1];
__device__ float g_tpad[NH];
__device__ float g_lpad[1];
__device__ float g_h2pad[NH];
__device__ float g_uwpad[NH];
__device__ float g_nw[ROWS_TOTAL];
__device__ float g_dualvars[NNODES];

// ---- host-side stream/events ----------------------------------------------------
static cudaStream_t g_sB;
static cudaEvent_t  g_ev[8];
namespace {
struct StreamInit {
    StreamInit() {
        cudaStreamCreateWithFlags(&g_sB, cudaStreamNonBlocking);
        for (int i = 0; i < 8; i++)
            cudaEventCreateWithFlags(&g_ev[i], cudaEventDisableTiming);
    }
};
static StreamInit s_streamInit;
}

__device__ __forceinline__ float sigmoidf_(float x) { return 1.f/(1.f+expf(-x)); }

// ---- bf16x2-split mma helpers ---------------------------------------------------
__device__ __forceinline__ void splitbf(float2 v, uint32_t &h, uint32_t &l) {
    asm("cvt.rn.bf16x2.f32 %0, %1, %2;" : "=r"(h) : "f"(v.y), "f"(v.x));
    float hx = __uint_as_float(h << 16);
    float hy = __uint_as_float(h & 0xffff0000u);
    asm("cvt.rn.bf16x2.f32 %0, %1, %2;" : "=r"(l) : "f"(v.y - hy), "f"(v.x - hx));
}
__device__ __forceinline__ void mma_bf16(float (&c)[4],
                                         uint32_t a0, uint32_t a1, uint32_t a2, uint32_t a3,
                                         uint32_t b0, uint32_t b1) {
    asm volatile("mma.sync.aligned.m16n8k16.row.col.f32.bf16.bf16.f32 "
                 "{%0,%1,%2,%3},{%4,%5,%6,%7},{%8,%9},{%0,%1,%2,%3};"
                 : "+f"(c[0]), "+f"(c[1]), "+f"(c[2]), "+f"(c[3])
                 : "r"(a0), "r"(a1), "r"(a2), "r"(a3), "r"(b0), "r"(b1));
}

// smem (uint32 units):
//   A hi/lo: [64 rows][68]  (row-major k-pairs, stride 68)
//   B hi/lo: [64 kp][136]   (k-major, stride 136 -> conflict-free ld+st)
#define AH_OFF 0
#define AL_OFF (64*68)
#define BH_OFF (2*64*68)
#define BL_OFF (2*64*68 + 64*136)
#define RED_OFF (2*64*68 + 2*64*136)
#define TMM_SMEM ((2*64*68 + 2*64*136 + 256)*4)

// stage A tile (64 rows x 128 k) as packed bf16x2 hi/lo, [r][kp] stride 68
__device__ __forceinline__ void stageA(uint32_t* sm_u, const float* __restrict__ A,
                                       int r0, int tid) {
    for (int i = tid; i < 64*64; i += 256) {
        int r = i >> 6, p = i & 63;
        float2 v = *(const float2*)(A + (size_t)(r0+r)*128 + p*2);
        uint32_t h, l; splitbf(v, h, l);
        sm_u[AH_OFF + r*68 + p] = h;
        sm_u[AL_OFF + r*68 + p] = l;
    }
}
// stage B tile: W row-major [k][n] (stride ws) -> smem [kp][n] stride 136
__device__ __forceinline__ void stageB(uint32_t* sm_u, const float* __restrict__ W,
                                       int colBase, int ws, int tid) {
    for (int i = tid; i < 64*128; i += 256) {
        int n = i & 127, kp = i >> 7;
        float2 v = make_float2(W[(2*kp)*ws + colBase + n], W[(2*kp+1)*ws + colBase + n]);
        uint32_t h, l; splitbf(v, h, l);
        sm_u[BH_OFF + kp*136 + n] = h;
        sm_u[BL_OFF + kp*136 + n] = l;
    }
}

// GEMM mainloop on pre-split tiles: pure LDS + MMA
__device__ __forceinline__ void tmm_core(const uint32_t* __restrict__ sm_u,
                                         float (&c)[2][4][4],
                                         int wm, int wn, int g, int t4) {
#pragma unroll
    for (int ks = 0; ks < 8; ks++) {
        const int ka = ks*8 + t4;
        uint32_t ah[2][4], al[2][4];
#pragma unroll
        for (int mt = 0; mt < 2; mt++) {
            int rb = wm*32 + mt*16 + g;
            ah[mt][0] = sm_u[AH_OFF + rb*68 + ka];
            ah[mt][1] = sm_u[AH_OFF + (rb+8)*68 + ka];
            ah[mt][2] = sm_u[AH_OFF + rb*68 + ka + 4];
            ah[mt][3] = sm_u[AH_OFF + (rb+8)*68 + ka + 4];
            al[mt][0] = sm_u[AL_OFF + rb*68 + ka];
            al[mt][1] = sm_u[AL_OFF + (rb+8)*68 + ka];
            al[mt][2] = sm_u[AL_OFF + rb*68 + ka + 4];
            al[mt][3] = sm_u[AL_OFF + (rb+8)*68 + ka + 4];
        }
        uint32_t bh[4][2], bl[4][2];
#pragma unroll
        for (int nt = 0; nt < 4; nt++) {
            int cb = wn*32 + nt*8 + g;
            bh[nt][0] = sm_u[BH_OFF + ka*136 + cb];
            bh[nt][1] = sm_u[BH_OFF + (ka+4)*136 + cb];
            bl[nt][0] = sm_u[BL_OFF + ka*136 + cb];
            bl[nt][1] = sm_u[BL_OFF + (ka+4)*136 + cb];
        }
#pragma unroll
        for (int mt = 0; mt < 2; mt++)
#pragma unroll
            for (int nt = 0; nt < 4; nt++) {
                mma_bf16(c[mt][nt], ah[mt][0],ah[mt][1],ah[mt][2],ah[mt][3], bh[nt][0],bh[nt][1]);
                mma_bf16(c[mt][nt], ah[mt][0],ah[mt][1],ah[mt][2],ah[mt][3], bl[nt][0],bl[nt][1]);
                mma_bf16(c[mt][nt], al[mt][0],al[mt][1],al[mt][2],al[mt][3], bh[nt][0],bh[nt][1]);
            }
    }
}

// ================= k_tnode: tnode/lnode GEMM =====================================
extern "C" __global__ void __launch_bounds__(256,2)
k_tnode(const float* __restrict__ Wgat, const float* __restrict__ b_gat,
        const float* __restrict__ a_gat, int asel) {
    extern __shared__ uint32_t sm_u[];
    float* red = (float*)(sm_u + RED_OFF);
    const float* A = asel ? g_hn1 : g_nodeenc;
    const int r0 = blockIdx.x * 64;
    const int tid = threadIdx.x;

    stageA(sm_u, A, r0, tid);
    stageB(sm_u, Wgat, 0, 128, tid);
    __syncthreads();

    const int warp = tid >> 5, lane = tid & 31;
    const int wm = warp & 1, wn = warp >> 1;
    const int g = lane >> 2, t4 = lane & 3;

    float c[2][4][4];
#pragma unroll
    for (int mt = 0; mt < 2; mt++)
#pragma unroll
        for (int nt = 0; nt < 4; nt++) {
            int col = wn*32 + nt*8 + 2*t4;
            c[mt][nt][0] = b_gat[col];  c[mt][nt][1] = b_gat[col+1];
            c[mt][nt][2] = b_gat[col];  c[mt][nt][3] = b_gat[col+1];
        }
    tmm_core(sm_u, c, wm, wn, g, t4);

#pragma unroll
    for (int mt = 0; mt < 2; mt++) {
        int rA = wm*32 + mt*16 + g;
        float lsA = 0.f, lsB = 0.f;
#pragma unroll
        for (int nt = 0; nt < 4; nt++) {
            int col = wn*32 + nt*8 + 2*t4;
            float t0 = tanhf(c[mt][nt][0]);
            float t1 = tanhf(c[mt][nt][1]);
            float t2 = tanhf(c[mt][nt][2]);
            float t3 = tanhf(c[mt][nt][3]);
            *(float2*)(g_tnode + (size_t)(r0+rA  )*128 + col) = make_float2(t0,t1);
            *(float2*)(g_tnode + (size_t)(r0+rA+8)*128 + col) = make_float2(t2,t3);
            float a0v = a_gat[col], a1v = a_gat[col+1];
            lsA += t0*a0v + t1*a1v;
            lsB += t2*a0v + t3*a1v;
        }
#pragma unroll
        for (int o = 1; o < 4; o <<= 1) {
            lsA += __shfl_xor_sync(0xffffffff, lsA, o);
            lsB += __shfl_xor_sync(0xffffffff, lsB, o);
        }
        if (t4 == 0) {
            red[rA*4 + wn]     = lsA;
            red[(rA+8)*4 + wn] = lsB;
        }
    }
    __syncthreads();
    if (tid < 64) {
        float l = red[tid*4] + red[tid*4+1] + red[tid*4+2] + red[tid*4+3];
        g_lnode[r0 + tid] = l;
    }
}

// ================= k_gh: gh chunks (grid (NNODES/64, 3)) =========================
extern "C" __global__ void __launch_bounds__(256,2)
k_gh(const float* __restrict__ Wh, int asel) {
    extern __shared__ uint32_t sm_u[];
    const float* A = asel ? g_hn1 : g_nodeenc;
    const int y  = blockIdx.y;
    const int r0 = blockIdx.x * 64;
    const int tid = threadIdx.x;

    stageA(sm_u, A, r0, tid);
    stageB(sm_u, Wh, y*128, 384, tid);
    __syncthreads();

    const int warp = tid >> 5, lane = tid & 31;
    const int wm = warp & 1, wn = warp >> 1;
    const int g = lane >> 2, t4 = lane & 3;

    float c[2][4][4];
#pragma unroll
    for (int mt = 0; mt < 2; mt++)
#pragma unroll
        for (int nt = 0; nt < 4; nt++)
            c[mt][nt][0]=c[mt][nt][1]=c[mt][nt][2]=c[mt][nt][3]=0.f;
    tmm_core(sm_u, c, wm, wn, g, t4);

#pragma unroll
    for (int mt = 0; mt < 2; mt++) {
        int rA = r0 + wm*32 + mt*16 + g;
#pragma unroll
        for (int nt = 0; nt < 4; nt++) {
            int col = y*128 + wn*32 + nt*8 + 2*t4;
            *(float2*)(g_gh + (size_t)rA*384 + col)     = make_float2(c[mt][nt][0], c[mt][nt][1]);
            *(float2*)(g_gh + (size_t)(rA+8)*384 + col) = make_float2(c[mt][nt][2], c[mt][nt][3]);
        }
    }
}

// ================= k_tmm: osel 0 = gx (grid x3), osel 3 = udec (grid x1) =========
extern "C" __global__ void __launch_bounds__(256,2)
k_tmm(const float* __restrict__ Wg, int asel, int osel) {
    extern __shared__ uint32_t sm_u[];
    const float* A = (asel==2) ? g_xnode : g_hn2;
    const float* W = (osel==3) ? g_wcomb : Wg;
    const int wstride = (osel==3) ? 128 : 384;
    const int colBase = blockIdx.y * 128;
    const int r0 = blockIdx.x * 64;
    const int tid = threadIdx.x;

    stageA(sm_u, A, r0, tid);
    stageB(sm_u, W, colBase, wstride, tid);
    __syncthreads();

    const int warp = tid >> 5, lane = tid & 31;
    const int wm = warp & 1, wn = warp >> 1;
    const int g = lane >> 2, t4 = lane & 3;

    float c[2][4][4];
#pragma unroll
    for (int mt = 0; mt < 2; mt++)
#pragma unroll
        for (int nt = 0; nt < 4; nt++)
            c[mt][nt][0]=c[mt][nt][1]=c[mt][nt][2]=c[mt][nt][3]=0.f;
    tmm_core(sm_u, c, wm, wn, g, t4);

    float* out = (osel==0) ? g_gx : g_uwn;
    const int ostride = (osel==0) ? 384 : 128;
#pragma unroll
    for (int mt = 0; mt < 2; mt++) {
        int rA = r0 + wm*32 + mt*16 + g;
#pragma unroll
        for (int nt = 0; nt < 4; nt++) {
            int col = colBase + wn*32 + nt*8 + 2*t4;
            *(float2*)(out + (size_t)rA*ostride + col)     = make_float2(c[mt][nt][0], c[mt][nt][1]);
            *(float2*)(out + (size_t)(rA+8)*ostride + col) = make_float2(c[mt][nt][2], c[mt][nt][3]);
        }
    }
}

// ================= encoding: one block per v, 16 batches, W_enc in smem =========
extern "C" __global__ void __launch_bounds__(128)
k_nodeencF(const float* __restrict__ emb,
           const float* __restrict__ nf,
           const float* __restrict__ W_enc,
           const float* __restrict__ b_enc) {
    const int v = blockIdx.x, t = threadIdx.x;
    __shared__ float Ws[(NE+NF)*NH];
    __shared__ float e_s[NE];
    __shared__ float red[128];
    for (int i = t; i < (NE+NF)*NH; i += 128) Ws[i] = W_enc[i];
    if (t < NE) e_s[t] = emb[v*NE + t];
    __syncthreads();
    red[t] = (t < NE) ? e_s[t]*e_s[t] : 0.f;
    __syncthreads();
    for (int s = 64; s > 0; s >>= 1) { if (t < s) red[t] += red[t+s]; __syncthreads(); }
    float inv = 1.f / fmaxf(sqrtf(red[0]), 1.f);
    float base = b_enc[t];
#pragma unroll 8
    for (int k = 0; k < NE; k++) base += e_s[k]*inv*Ws[k*NH + t];
#pragma unroll
    for (int b = 0; b < NB; b++) {
        const float* nfr = nf + (size_t)(b*NV + v)*NF;
        float acc = base;
#pragma unroll
        for (int k = 0; k < NF; k++) acc += nfr[k]*Ws[(NE+k)*NH + t];
        g_nodeenc[(size_t)(b*NV + v)*NH + t] = acc;
    }
}

// ================= wprep + pads fused ============================================
extern "C" __global__ void k_pads(const float* __restrict__ bg,
                                  const float* __restrict__ Wh,
                                  const float* __restrict__ W_gat,
                                  const float* __restrict__ b_gat,
                                  const float* __restrict__ a_gat,
                                  const float* __restrict__ W1) {
    int t = threadIdx.x;  // 512
    __shared__ float h1p[128], ghp[384], red[128], h2ps[128];
    for (int i = t; i < 16384; i += 512) {
        int k = i >> 7, c = i & 127;
        float v;
        if (c < 64) v = W1[k*64 + c] + W1[(128+k)*64 + c];
        else        v = W1[(128+k)*64 + (c-64)];
        g_wcomb[i] = v;
    }
    if (t < 128) h1p[t] = (1.f - sigmoidf_(bg[t])) * tanhf(bg[256+t]);
    __syncthreads();
    if (t < 384) {
        float s = 0.f;
#pragma unroll 8
        for (int k = 0; k < 128; k++) s += h1p[k]*Wh[k*384 + t];
        ghp[t] = s;
    } else {
        int c = t - 384;
        float s = b_gat[c];
#pragma unroll 8
        for (int k = 0; k < 128; k++) s += h1p[k]*W_gat[k*128 + c];
        float t2 = tanhf(s);
        g_tpad[c] = t2;
        red[c] = t2*a_gat[c];
    }
    __syncthreads();
    for (int st = 64; st > 0; st >>= 1) { if (t < st) red[t] += red[t+st]; __syncthreads(); }
    if (t == 0) g_lpad[0] = red[0];
    if (t < 128) {
        float z = sigmoidf_(bg[t] + ghp[t]);
        float r = sigmoidf_(bg[128+t] + ghp[128+t]);
        float cand = tanhf(bg[256+t] + r*ghp[256+t]);
        float h2p = z*h1p[t] + (1.f - z)*cand;
        g_h2pad[t] = h2p;
        h2ps[t] = h2p;
        float tb = tanhf(b_gat[t]);
        g_tpad0[t] = tb;
        red[t] = tb*a_gat[t];
    }
    __syncthreads();
    for (int st = 64; st > 0; st >>= 1) { if (t < st) red[t] += red[t+st]; __syncthreads(); }
    if (t == 0) g_lpad0[0] = red[0];
    if (t < 128) {
        float u = 0.f;
#pragma unroll 8
        for (int k = 0; k < 128; k++) u += h2ps[k]*g_wcomb[k*128 + t];
        g_uwpad[t] = u;
    }
}

// ================= warp-per-node attention + x ==================================
extern "C" __global__ void k_attn(const int* __restrict__ adj,
                                  const int* __restrict__ num_nodes, int layer) {
    const int tid = threadIdx.x;
    const int lane = tid & 31;
    const int n = blockIdx.x*8 + (tid >> 5);
    const int b = n >> 10;
    const int nn = num_nodes[b];
    const float* tpad = layer ? g_tpad : g_tpad0;
    const float lpadv = (layer ? g_lpad[0] : g_lpad0[0]) - BIGF;

    int adjs = 0; float val = 0.f; float lg = -1e30f;
    if (lane < 16) {
        int a = adj[n*16 + lane];
        val = (a == nn) ? 0.f : 1.f;
        adjs = b*NV + min(a, NV-1);
        lg = (val != 0.f) ? g_lnode[adjs] : lpadv;
    }
    float mx = lg;
#pragma unroll
    for (int o = 16; o; o >>= 1) mx = fmaxf(mx, __shfl_xor_sync(0xffffffffu, mx, o));
    float e = (lane < 16) ? expf(lg - mx) : 0.f;
    float ssum = e;
#pragma unroll
    for (int o = 16; o; o >>= 1) ssum += __shfl_xor_sync(0xffffffffu, ssum, o);
    float at = e / ssum;

    float4 tp4 = *(const float4*)(tpad + lane*4);
    float4 msg = make_float4(0.f, 0.f, 0.f, 0.f);
#pragma unroll
    for (int d = 0; d < 16; d++) {
        float atd = __shfl_sync(0xffffffffu, at, d);
        int   rwd = __shfl_sync(0xffffffffu, adjs, d);
        float vdd = __shfl_sync(0xffffffffu, val, d);
        float4 tv = (vdd != 0.f) ? *(const float4*)(g_tnode + (size_t)rwd*128 + lane*4) : tp4;
        msg.x += atd*tv.x; msg.y += atd*tv.y; msg.z += atd*tv.z; msg.w += atd*tv.w;
    }
    float4 ne = *(const float4*)(g_nodeenc + (size_t)n*128 + lane*4);
    float4 o;
    o.x = tanhf(msg.x + ne.x);
    o.y = tanhf(msg.y + ne.y);
    o.z = tanhf(msg.z + ne.z);
    o.w = tanhf(msg.w + ne.w);
    *(float4*)(g_xnode + (size_t)n*128 + lane*4) = o;
}

// ================= node-level GRU combine (float4) ===============================
extern "C" __global__ void k_combnode(const float* __restrict__ bg, int mode) {
    int idx = blockIdx.x*256 + threadIdx.x;   // NNODES*32 threads total
    int n = idx >> 5;
    int c = (idx & 31)*4;
    const float* hprev = mode ? g_hn1 : g_nodeenc;
    float* out         = mode ? g_hn2 : g_hn1;
    size_t i = (size_t)n*384;
    float4 gxz = *(const float4*)(g_gx + i + c);
    float4 gxr = *(const float4*)(g_gx + i + 128 + c);
    float4 gxc = *(const float4*)(g_gx + i + 256 + c);
    float4 ghz = *(const float4*)(g_gh + i + c);
    float4 ghr = *(const float4*)(g_gh + i + 128 + c);
    float4 ghc = *(const float4*)(g_gh + i + 256 + c);
    float4 hp  = *(const float4*)(hprev + (size_t)n*128 + c);
    float4 bz = *(const float4*)(bg + c);
    float4 br = *(const float4*)(bg + 128 + c);
    float4 bc = *(const float4*)(bg + 256 + c);
    float4 o;
    {
        float z = sigmoidf_(gxz.x + ghz.x + bz.x);
        float r = sigmoidf_(gxr.x + ghr.x + br.x);
        o.x = z*hp.x + (1.f - z)*tanhf(gxc.x + bc.x + r*ghc.x);
    }
    {
        float z = sigmoidf_(gxz.y + ghz.y + bz.y);
        float r = sigmoidf_(gxr.y + ghr.y + br.y);
        o.y = z*hp.y + (1.f - z)*tanhf(gxc.y + bc.y + r*ghc.y);
    }
    {
        float z = sigmoidf_(gxz.z + ghz.z + bz.z);
        float r = sigmoidf_(gxr.z + ghr.z + br.z);
        o.z = z*hp.z + (1.f - z)*tanhf(gxc.z + bc.z + r*ghc.z);
    }
    {
        float z = sigmoidf_(gxz.w + ghz.w + bz.w);
        float r = sigmoidf_(gxr.w + ghr.w + br.w);
        o.w = z*hp.w + (1.f - z)*tanhf(gxc.w + bc.w + r*ghc.w);
    }
    *(float4*)(out + (size_t)n*128 + c) = o;
}

// ================= per-edge nw (float2) ==========================================
extern "C" __global__ void k_nw(const float* __restrict__ b1,
                                const float* __restrict__ W2,
                                const float* __restrict__ b2,
                                const int* __restrict__ adj,
                                const int* __restrict__ num_nodes) {
    int e = blockIdx.x*8 + (threadIdx.x >> 5);
    int lane = threadIdx.x & 31;
    int b = e / VD;
    int d = e & 15;
    int nn = num_nodes[b];
    int a_raw = adj[e];
    int an = min(a_raw, NV-1);
    bool ve = (a_raw != nn);
    int a2_raw = adj[(b*NV + an)*ND + (d ^ 1)];
    int an2 = min(a2_raw, NV-1);
    bool ve2 = (a2_raw != nn);
    const float* rowA = ve  ? (g_uwn + (size_t)(b*NV + an)*NH)        : g_uwpad;
    const float* rowB = ve2 ? (g_uwn + (size_t)(b*NV + an2)*NH + 64)  : (g_uwpad + 64);
    float2 a2 = *(const float2*)(rowA + lane*2);
    float2 c2 = *(const float2*)(rowB + lane*2);
    float2 b12 = *(const float2*)(b1 + lane*2);
    float2 w22 = *(const float2*)(W2 + lane*2);
    float s = tanhf(a2.x + c2.x + b12.x)*w22.x + tanhf(a2.y + c2.y + b12.y)*w22.y;
#pragma unroll
    for (int o = 16; o > 0; o >>= 1) s += __shfl_down_sync(0xffffffff, s, o);
    if (lane == 0) g_nw[e] = s + b2[0];
}

// ================= dual vars (split-K matvec) ====================================
extern "C" __global__ void k_dualvars(const float* __restrict__ W1,
                                      const float* __restrict__ b1,
                                      const float* __restrict__ W2,
                                      const float* __restrict__ b2,
                                      const int* __restrict__ adj,
                                      const int* __restrict__ num_nodes) {
    int bv = blockIdx.x, t = threadIdx.x;  // 128 threads
    int b = bv >> 10;
    __shared__ float ns[128];
    __shared__ float part[128];
    __shared__ float hid[64];
    __shared__ int adjs[16];
    __shared__ float vals[16];
    if (t < 16) {
        int a = adj[bv*16 + t];
        vals[t] = (a == num_nodes[b]) ? 0.f : 1.f;
        adjs[t] = b*NV + min(a, NV-1);
    }
    __syncthreads();
    float hpad = g_h2pad[t];
    float s = 0.f;
#pragma unroll
    for (int d = 0; d < 16; d++)
        s += (vals[d] != 0.f) ? g_hn2[(size_t)adjs[d]*128 + t] : hpad;
    ns[t] = s;
    __syncthreads();
    {
        int j = t & 63;
        int k0 = (t >> 6)*64;
        float a = 0.f;
#pragma unroll 8
        for (int k = 0; k < 64; k++) a += ns[k0+k]*W1[(k0+k)*NHD + j];
        part[t] = a;
    }
    __syncthreads();
    if (t < 64) hid[t] = tanhf(part[t] + part[t+64] + b1[t]) * W2[t];
    __syncthreads();
    for (int st = 32; st > 0; st >>= 1) { if (t < st) hid[t] += hid[t+st]; __syncthreads(); }
    if (t == 0) g_dualvars[bv] = fmaxf(hid[0] + b2[0], 0.f);
}

// ================= fused tail: dest softmax + sparsemax + flow + dual + out ======
#define TAILSM ((3*VD + 1024)*4)
extern "C" __global__ void __launch_bounds__(1024,1)
k_tail(const float* __restrict__ demands, const int* __restrict__ inv_adj,
       const int* __restrict__ adj, const int* __restrict__ num_nodes,
       float* __restrict__ out) {
    extern __shared__ float sm[];
    float* dest_s = sm;
    float* f0  = sm + VD;
    float* f1  = sm + 2*VD;
    float* red = sm + 3*VD;
    const int b = blockIdx.x, v = threadIdx.x;
    const int nn = num_nodes[b];
    const int base = (b*NV + v)*ND;
    const float dem = demands[b*NV + v];

    int ia[16];
    {
        float w[16]; float mx = -1e30f;
#pragma unroll
        for (int d = 0; d < 16; d++) {
            int iar = inv_adj[base + d];
            float m = (iar == nn) ? 1.f : 0.f;
            ia[d] = min(iar, NV-1);
            float val = g_nw[(b*NV + ia[d])*ND + d] - BIGF*m;
            w[d] = val; mx = fmaxf(mx, val);
        }
        float ssum = 0.f;
#pragma unroll
        for (int d = 0; d < 16; d++) { w[d] = expf(w[d]-mx); ssum += w[d]; }
        float inv = 1.f/ssum;
#pragma unroll
        for (int d = 0; d < 16; d++) dest_s[d*NV + v] = w[d]*inv;
    }
    __syncthreads();

    float nrm[16];
    {
        float z[16], valid[16];
#pragma unroll
        for (int d = 0; d < 16; d++) {
            int a = adj[base + d];
            float m = (a == nn) ? 1.f : 0.f;
            valid[d] = 1.f - m;
            z[d] = dest_s[d*NV + min(a, NV-1)] - BIGF*m;
        }
        float zs[16];
        for (int d = 0; d < 16; d++) zs[d] = z[d];
        for (int i = 1; i < 16; i++) {
            float key = zs[i]; int j = i-1;
            while (j >= 0 && zs[j] < key) { zs[j+1] = zs[j]; j--; }
            zs[j+1] = key;
        }
        float csum = 0.f, zck = 0.f; int kz = 1;
        for (int k = 1; k <= 16; k++) {
            csum += zs[k-1];
            if (1.f + (float)k*zs[k-1] > csum) { kz = k; zck = csum; }
        }
        float tau = (zck - 1.f)/(float)kz;
#pragma unroll
        for (int d = 0; d < 16; d++)
            nrm[d] = fmaxf(z[d] - tau, 0.f) * valid[d];
    }

#pragma unroll
    for (int d = 0; d < 16; d++) f0[d*NV + v] = 0.f;
    __syncthreads();
    float* cur = f0; float* nxt = f1;
    for (int it = 0; it < 10; it++) {
        float inflow = 0.f;
#pragma unroll
        for (int d = 0; d < 16; d++) inflow += cur[d*NV + ia[d]];
        float val = fmaxf(inflow - dem, 0.f);
#pragma unroll
        for (int d = 0; d < 16; d++) nxt[d*NV + v] = nrm[d]*val;
        __syncthreads();
        float* tmp = cur; cur = nxt; nxt = tmp;
    }
    float c = 0.f;
#pragma unroll
    for (int d = 0; d < 16; d++) { float f = cur[d*NV + v]; c += f*f; }

    float dvv = g_dualvars[b*NV + v];
    float ddem = dvv*dem;
    float ec = 0.f;
#pragma unroll
    for (int d = 0; d < 16; d++) {
        int a = adj[base + d];
        float m = (a == nn) ? 1.f : 0.f;
        float valid = 1.f - m;
        float dual = m*dvv;
        float dtr = g_dualvars[b*NV + min(a, NV-1)]*valid;
        float dd = dtr - dual;
        float f = 0.f, vel = 0.f;
#pragma unroll
        for (int it = 0; it < 10; it++) {
            float grad = 2.f*f + dd;
            vel = 0.9f*vel - 0.01f*grad;
            f = fmaxf(f + vel, 0.f);
        }
        float df = f*valid;
        ec += df*df + dd*df;
    }
    red[v] = c - ec + ddem;
    __syncthreads();
    for (int s = 512; s > 0; s >>= 1) { if (v < s) red[v] += red[v+s]; __syncthreads(); }
    if (v == 0) out[b] = red[0];
}

extern "C" void kernel_launch(void* const* d_in, const int* in_sizes, int n_in,
                              void* d_out, int out_size) {
    const float* demands       = (const float*)d_in[0];
    const float* node_features = (const float*)d_in[1];
    const float* node_emb      = (const float*)d_in[4];
    const float* W_enc   = (const float*)d_in[5];
    const float* b_enc   = (const float*)d_in[6];
    const float* W_gat   = (const float*)d_in[7];
    const float* b_gat   = (const float*)d_in[8];
    const float* a_gat   = (const float*)d_in[9];
    const float* W_gru_x = (const float*)d_in[10];
    const float* W_gru_h = (const float*)d_in[11];
    const float* b_gru   = (const float*)d_in[12];
    const float* W_dec1  = (const float*)d_in[13];
    const float* b_dec1  = (const float*)d_in[14];
    const float* W_dec2  = (const float*)d_in[15];
    const float* b_dec2  = (const float*)d_in[16];
    const float* W_dual1 = (const float*)d_in[17];
    const float* b_dual1 = (const float*)d_in[18];
    const float* W_dual2 = (const float*)d_in[19];
    const float* b_dual2 = (const float*)d_in[20];
    const int* adj       = (const int*)d_in[21];
    const int* inv_adj   = (const int*)d_in[22];
    const int* num_nodes = (const int*)d_in[26];
    float* out = (float*)d_out;

    cudaFuncSetAttribute(k_tnode, cudaFuncAttributeMaxDynamicSharedMemorySize, TMM_SMEM);
    cudaFuncSetAttribute(k_gh,    cudaFuncAttributeMaxDynamicSharedMemorySize, TMM_SMEM);
    cudaFuncSetAttribute(k_tmm,   cudaFuncAttributeMaxDynamicSharedMemorySize, TMM_SMEM);
    cudaFuncSetAttribute(k_tail,  cudaFuncAttributeMaxDynamicSharedMemorySize, TAILSM);

    dim3 g3(NNODES/64, 3);
    dim3 g1(NNODES/64, 1);

    // fork side stream off the (capturing) main stream
    cudaEventRecord(g_ev[0], 0);
    cudaStreamWaitEvent(g_sB, g_ev[0], 0);

    // main: node encoding ; side: pads
    k_nodeencF<<<NV, 128>>>(node_emb, node_features, W_enc, b_enc);
    cudaEventRecord(g_ev[1], 0);                                     // nodeenc ready
    k_pads<<<1, 512, 0, g_sB>>>(b_gru, W_gru_h, W_gat, b_gat, a_gat, W_dec1);
    cudaEventRecord(g_ev[2], g_sB);                                  // pads ready

    // ---- layer 1 ----
    cudaStreamWaitEvent(g_sB, g_ev[1], 0);
    k_gh<<<g3, 256, TMM_SMEM, g_sB>>>(W_gru_h, 0);                   // side: gh1
    cudaEventRecord(g_ev[3], g_sB);

    k_tnode<<<NNODES/64, 256, TMM_SMEM>>>(W_gat, b_gat, a_gat, 0);   // main: tnode1
    cudaStreamWaitEvent(0, g_ev[2], 0);                              // pads needed by attn
    k_attn<<<NNODES/8, 256>>>(adj, num_nodes, 0);
    k_tmm<<<g3, 256, TMM_SMEM>>>(W_gru_x, 2, 0);                     // gx1
    cudaStreamWaitEvent(0, g_ev[3], 0);                              // gh1 needed
    k_combnode<<<NNODES/8, 256>>>(b_gru, 0);                         // -> H1
    cudaEventRecord(g_ev[4], 0);                                     // H1 ready

    // ---- layer 2 ----
    cudaStreamWaitEvent(g_sB, g_ev[4], 0);
    k_gh<<<g3, 256, TMM_SMEM, g_sB>>>(W_gru_h, 1);                   // side: gh2
    cudaEventRecord(g_ev[5], g_sB);

    k_tnode<<<NNODES/64, 256, TMM_SMEM>>>(W_gat, b_gat, a_gat, 1);   // main: tnode2
    k_attn<<<NNODES/8, 256>>>(adj, num_nodes, 1);
    k_tmm<<<g3, 256, TMM_SMEM>>>(W_gru_x, 2, 0);                     // gx2
    cudaStreamWaitEvent(0, g_ev[5], 0);                              // gh2 needed
    k_combnode<<<NNODES/8, 256>>>(b_gru, 1);                         // -> H2
    cudaEventRecord(g_ev[6], 0);                                     // H2 ready

    // ---- tail: dualvars on side stream, decoder chain on main ----
    cudaStreamWaitEvent(g_sB, g_ev[6], 0);
    k_dualvars<<<NNODES, 128, 0, g_sB>>>(W_dual1, b_dual1, W_dual2, b_dual2, adj, num_nodes);
    cudaEventRecord(g_ev[7], g_sB);

    k_tmm<<<g1, 256, TMM_SMEM>>>(nullptr, 3, 3);                     // uwn = H2 @ wcomb
    k_nw<<<ROWS_TOTAL/8, 256>>>(b_dec1, W_dec2, b_dec2, adj, num_nodes);
    cudaStreamWaitEvent(0, g_ev[7], 0);                              // dualvars needed
    k_tail<<<NB, 1024, TAILSM>>>(demands, inv_adj, adj, num_nodes, out);
}

// round 16
// speedup vs baseline: 1.1717x; 1.0637x over previous
#include <cuda_runtime.h>
#include <math.h>
#include <stdint.h>

#define NB 16
#define NV 1024
#define ND 16
#define NE 64
#define NF 16
#define NH 128
#define NHD 64
#define BIGF 1e9f
#define VD (NV*ND)
#define ROWS_TOTAL (NB*VD)
#define NNODES (NB*NV)

// ---- scratch ------------------------------------------------------------------
__device__ float g_nodeenc[NNODES*NH];
__device__ float g_xnode[NNODES*NH];
__device__ float g_tnode[NNODES*NH];
__device__ float g_lnode[NNODES];
__device__ float g_hn1[NNODES*NH];
__device__ float g_hn2[NNODES*NH];
__device__ float g_gx[NNODES*3*NH];
__device__ float g_gh[NNODES*3*NH];
__device__ float g_uwn[NNODES*NH];
__device__ float g_wcomb[NH*NH];
__device__ float g_tpad0[NH];
__device__ float g_lpad0[1];
__device__ float g_tpad[NH];
__device__ float g_lpad[1];
__device__ float g_h2pad[NH];
__device__ float g_uwpad[NH];
__device__ float g_nw[ROWS_TOTAL];
__device__ float g_dualvars[NNODES];
// pre-split weight panels: chunk 0=Wgat, 1..3=Wh, 4..6=Wx, 7=wcomb ([kp*128+n])
__device__ uint32_t g_wsh[8*8192];
__device__ uint32_t g_wsl[8*8192];

// ---- host-side stream/events ----------------------------------------------------
static cudaStream_t g_sB;
static cudaEvent_t  g_ev[10];
namespace {
struct StreamInit {
    StreamInit() {
        cudaStreamCreateWithFlags(&g_sB, cudaStreamNonBlocking);
        for (int i = 0; i < 10; i++)
            cudaEventCreateWithFlags(&g_ev[i], cudaEventDisableTiming);
    }
};
static StreamInit s_streamInit;
}

__device__ __forceinline__ float sigmoidf_(float x) { return 1.f/(1.f+expf(-x)); }

// ---- bf16x2-split mma helpers ---------------------------------------------------
__device__ __forceinline__ void splitbf(float2 v, uint32_t &h, uint32_t &l) {
    asm("cvt.rn.bf16x2.f32 %0, %1, %2;" : "=r"(h) : "f"(v.y), "f"(v.x));
    float hx = __uint_as_float(h << 16);
    float hy = __uint_as_float(h & 0xffff0000u);
    asm("cvt.rn.bf16x2.f32 %0, %1, %2;" : "=r"(l) : "f"(v.y - hy), "f"(v.x - hx));
}
__device__ __forceinline__ void mma_bf16(float (&c)[4],
                                         uint32_t a0, uint32_t a1, uint32_t a2, uint32_t a3,
                                         uint32_t b0, uint32_t b1) {
    asm volatile("mma.sync.aligned.m16n8k16.row.col.f32.bf16.bf16.f32 "
                 "{%0,%1,%2,%3},{%4,%5,%6,%7},{%8,%9},{%0,%1,%2,%3};"
                 : "+f"(c[0]), "+f"(c[1]), "+f"(c[2]), "+f"(c[3])
                 : "r"(a0), "r"(a1), "r"(a2), "r"(a3), "r"(b0), "r"(b1));
}

// smem (uint32 units):
//   A hi/lo: [64 rows][68]  (row-major k-pairs, stride 68)
//   B hi/lo: [64 kp][136]   (k-major, stride 136 -> conflict-free ld+st)
#define AH_OFF 0
#define AL_OFF (64*68)
#define BH_OFF (2*64*68)
#define BL_OFF (2*64*68 + 64*136)
#define RED_OFF (2*64*68 + 2*64*136)
#define TMM_SMEM ((2*64*68 + 2*64*136 + 256)*4)

// stage A tile (64 rows x 128 k): float4 loads, split, uint2 stores
__device__ __forceinline__ void stageA(uint32_t* sm_u, const float* __restrict__ A,
                                       int r0, int tid) {
    for (int i = tid; i < 2048; i += 256) {
        int idx = i*2;                 // pair index (even)
        int r = idx >> 6, p = idx & 63;
        float4 v = *(const float4*)(A + (size_t)(r0+r)*128 + p*2);
        uint32_t h0, l0, h1, l1;
        splitbf(make_float2(v.x, v.y), h0, l0);
        splitbf(make_float2(v.z, v.w), h1, l1);
        *(uint2*)(sm_u + AH_OFF + r*68 + p) = make_uint2(h0, h1);
        *(uint2*)(sm_u + AL_OFF + r*68 + p) = make_uint2(l0, l1);
    }
}
// stage B tile from pre-split global: pure uint4 copy
__device__ __forceinline__ void stageB(uint32_t* sm_u, int chunk, int tid) {
    const uint32_t* wh = g_wsh + chunk*8192;
    const uint32_t* wl = g_wsl + chunk*8192;
    for (int i = tid; i < 2048; i += 256) {
        int idx = i*4;
        int n = idx & 127, kp = idx >> 7;
        *(uint4*)(sm_u + BH_OFF + kp*136 + n) = *(const uint4*)(wh + idx);
        *(uint4*)(sm_u + BL_OFF + kp*136 + n) = *(const uint4*)(wl + idx);
    }
}

// GEMM mainloop on pre-split tiles: pure LDS + MMA
__device__ __forceinline__ void tmm_core(const uint32_t* __restrict__ sm_u,
                                         float (&c)[2][4][4],
                                         int wm, int wn, int g, int t4) {
#pragma unroll
    for (int ks = 0; ks < 8; ks++) {
        const int ka = ks*8 + t4;
        uint32_t ah[2][4], al[2][4];
#pragma unroll
        for (int mt = 0; mt < 2; mt++) {
            int rb = wm*32 + mt*16 + g;
            ah[mt][0] = sm_u[AH_OFF + rb*68 + ka];
            ah[mt][1] = sm_u[AH_OFF + (rb+8)*68 + ka];
            ah[mt][2] = sm_u[AH_OFF + rb*68 + ka + 4];
            ah[mt][3] = sm_u[AH_OFF + (rb+8)*68 + ka + 4];
            al[mt][0] = sm_u[AL_OFF + rb*68 + ka];
            al[mt][1] = sm_u[AL_OFF + (rb+8)*68 + ka];
            al[mt][2] = sm_u[AL_OFF + rb*68 + ka + 4];
            al[mt][3] = sm_u[AL_OFF + (rb+8)*68 + ka + 4];
        }
        uint32_t bh[4][2], bl[4][2];
#pragma unroll
        for (int nt = 0; nt < 4; nt++) {
            int cb = wn*32 + nt*8 + g;
            bh[nt][0] = sm_u[BH_OFF + ka*136 + cb];
            bh[nt][1] = sm_u[BH_OFF + (ka+4)*136 + cb];
            bl[nt][0] = sm_u[BL_OFF + ka*136 + cb];
            bl[nt][1] = sm_u[BL_OFF + (ka+4)*136 + cb];
        }
#pragma unroll
        for (int mt = 0; mt < 2; mt++)
#pragma unroll
            for (int nt = 0; nt < 4; nt++) {
                mma_bf16(c[mt][nt], ah[mt][0],ah[mt][1],ah[mt][2],ah[mt][3], bh[nt][0],bh[nt][1]);
                mma_bf16(c[mt][nt], ah[mt][0],ah[mt][1],ah[mt][2],ah[mt][3], bl[nt][0],bl[nt][1]);
                mma_bf16(c[mt][nt], al[mt][0],al[mt][1],al[mt][2],al[mt][3], bh[nt][0],bh[nt][1]);
            }
    }
}

// ================= k_wsplit: pre-split weight panels 0..6 ========================
extern "C" __global__ void k_wsplit(const float* __restrict__ Wgat,
                                    const float* __restrict__ Wh,
                                    const float* __restrict__ Wx) {
    const int chunk = blockIdx.x;    // 0..6
    const float* W;
    int ws, colBase;
    if (chunk == 0)      { W = Wgat; ws = 128; colBase = 0; }
    else if (chunk < 4)  { W = Wh;   ws = 384; colBase = (chunk-1)*128; }
    else                 { W = Wx;   ws = 384; colBase = (chunk-4)*128; }
    for (int i = threadIdx.x; i < 8192; i += 256) {
        int n = i & 127, kp = i >> 7;
        float2 v = make_float2(W[(2*kp)*ws + colBase + n], W[(2*kp+1)*ws + colBase + n]);
        uint32_t h, l; splitbf(v, h, l);
        g_wsh[chunk*8192 + i] = h;
        g_wsl[chunk*8192 + i] = l;
    }
}

// ================= k_tnode: tnode/lnode GEMM (chunk 0) ===========================
extern "C" __global__ void __launch_bounds__(256,2)
k_tnode(const float* __restrict__ b_gat, const float* __restrict__ a_gat, int asel) {
    extern __shared__ uint32_t sm_u[];
    float* red = (float*)(sm_u + RED_OFF);
    const float* A = asel ? g_hn1 : g_nodeenc;
    const int r0 = blockIdx.x * 64;
    const int tid = threadIdx.x;

    stageA(sm_u, A, r0, tid);
    stageB(sm_u, 0, tid);
    __syncthreads();

    const int warp = tid >> 5, lane = tid & 31;
    const int wm = warp & 1, wn = warp >> 1;
    const int g = lane >> 2, t4 = lane & 3;

    float c[2][4][4];
#pragma unroll
    for (int mt = 0; mt < 2; mt++)
#pragma unroll
        for (int nt = 0; nt < 4; nt++) {
            int col = wn*32 + nt*8 + 2*t4;
            c[mt][nt][0] = b_gat[col];  c[mt][nt][1] = b_gat[col+1];
            c[mt][nt][2] = b_gat[col];  c[mt][nt][3] = b_gat[col+1];
        }
    tmm_core(sm_u, c, wm, wn, g, t4);

#pragma unroll
    for (int mt = 0; mt < 2; mt++) {
        int rA = wm*32 + mt*16 + g;
        float lsA = 0.f, lsB = 0.f;
#pragma unroll
        for (int nt = 0; nt < 4; nt++) {
            int col = wn*32 + nt*8 + 2*t4;
            float t0 = tanhf(c[mt][nt][0]);
            float t1 = tanhf(c[mt][nt][1]);
            float t2 = tanhf(c[mt][nt][2]);
            float t3 = tanhf(c[mt][nt][3]);
            *(float2*)(g_tnode + (size_t)(r0+rA  )*128 + col) = make_float2(t0,t1);
            *(float2*)(g_tnode + (size_t)(r0+rA+8)*128 + col) = make_float2(t2,t3);
            float a0v = a_gat[col], a1v = a_gat[col+1];
            lsA += t0*a0v + t1*a1v;
            lsB += t2*a0v + t3*a1v;
        }
#pragma unroll
        for (int o = 1; o < 4; o <<= 1) {
            lsA += __shfl_xor_sync(0xffffffff, lsA, o);
            lsB += __shfl_xor_sync(0xffffffff, lsB, o);
        }
        if (t4 == 0) {
            red[rA*4 + wn]     = lsA;
            red[(rA+8)*4 + wn] = lsB;
        }
    }
    __syncthreads();
    if (tid < 64) {
        float l = red[tid*4] + red[tid*4+1] + red[tid*4+2] + red[tid*4+3];
        g_lnode[r0 + tid] = l;
    }
}

// ================= k_gh: gh chunks (grid (NNODES/64, 3), chunk 1+y) ==============
extern "C" __global__ void __launch_bounds__(256,2)
k_gh(int asel) {
    extern __shared__ uint32_t sm_u[];
    const float* A = asel ? g_hn1 : g_nodeenc;
    const int y  = blockIdx.y;
    const int r0 = blockIdx.x * 64;
    const int tid = threadIdx.x;

    stageA(sm_u, A, r0, tid);
    stageB(sm_u, 1 + y, tid);
    __syncthreads();

    const int warp = tid >> 5, lane = tid & 31;
    const int wm = warp & 1, wn = warp >> 1;
    const int g = lane >> 2, t4 = lane & 3;

    float c[2][4][4];
#pragma unroll
    for (int mt = 0; mt < 2; mt++)
#pragma unroll
        for (int nt = 0; nt < 4; nt++)
            c[mt][nt][0]=c[mt][nt][1]=c[mt][nt][2]=c[mt][nt][3]=0.f;
    tmm_core(sm_u, c, wm, wn, g, t4);

#pragma unroll
    for (int mt = 0; mt < 2; mt++) {
        int rA = r0 + wm*32 + mt*16 + g;
#pragma unroll
        for (int nt = 0; nt < 4; nt++) {
            int col = y*128 + wn*32 + nt*8 + 2*t4;
            *(float2*)(g_gh + (size_t)rA*384 + col)     = make_float2(c[mt][nt][0], c[mt][nt][1]);
            *(float2*)(g_gh + (size_t)(rA+8)*384 + col) = make_float2(c[mt][nt][2], c[mt][nt][3]);
        }
    }
}

// ================= k_tmm: osel 0 = gx (chunk 4+y), osel 3 = udec (chunk 7) =======
extern "C" __global__ void __launch_bounds__(256,2)
k_tmm(int asel, int osel) {
    extern __shared__ uint32_t sm_u[];
    const float* A = (asel==2) ? g_xnode : g_hn2;
    const int chunk = (osel==3) ? 7 : (4 + blockIdx.y);
    const int colBase = blockIdx.y * 128;
    const int r0 = blockIdx.x * 64;
    const int tid = threadIdx.x;

    stageA(sm_u, A, r0, tid);
    stageB(sm_u, chunk, tid);
    __syncthreads();

    const int warp = tid >> 5, lane = tid & 31;
    const int wm = warp & 1, wn = warp >> 1;
    const int g = lane >> 2, t4 = lane & 3;

    float c[2][4][4];
#pragma unroll
    for (int mt = 0; mt < 2; mt++)
#pragma unroll
        for (int nt = 0; nt < 4; nt++)
            c[mt][nt][0]=c[mt][nt][1]=c[mt][nt][2]=c[mt][nt][3]=0.f;
    tmm_core(sm_u, c, wm, wn, g, t4);

    float* out = (osel==0) ? g_gx : g_uwn;
    const int ostride = (osel==0) ? 384 : 128;
#pragma unroll
    for (int mt = 0; mt < 2; mt++) {
        int rA = r0 + wm*32 + mt*16 + g;
#pragma unroll
        for (int nt = 0; nt < 4; nt++) {
            int col = colBase + wn*32 + nt*8 + 2*t4;
            *(float2*)(out + (size_t)rA*ostride + col)     = make_float2(c[mt][nt][0], c[mt][nt][1]);
            *(float2*)(out + (size_t)(rA+8)*ostride + col) = make_float2(c[mt][nt][2], c[mt][nt][3]);
        }
    }
}

// ================= encoding: one block per v, 16 batches, W_enc in smem =========
extern "C" __global__ void __launch_bounds__(128)
k_nodeencF(const float* __restrict__ emb,
           const float* __restrict__ nf,
           const float* __restrict__ W_enc,
           const float* __restrict__ b_enc) {
    const int v = blockIdx.x, t = threadIdx.x;
    __shared__ float Ws[(NE+NF)*NH];
    __shared__ float e_s[NE];
    __shared__ float red[128];
    for (int i = t; i < (NE+NF)*NH; i += 128) Ws[i] = W_enc[i];
    if (t < NE) e_s[t] = emb[v*NE + t];
    __syncthreads();
    red[t] = (t < NE) ? e_s[t]*e_s[t] : 0.f;
    __syncthreads();
    for (int s = 64; s > 0; s >>= 1) { if (t < s) red[t] += red[t+s]; __syncthreads(); }
    float inv = 1.f / fmaxf(sqrtf(red[0]), 1.f);
    float base = b_enc[t];
#pragma unroll 8
    for (int k = 0; k < NE; k++) base += e_s[k]*inv*Ws[k*NH + t];
#pragma unroll
    for (int b = 0; b < NB; b++) {
        const float* nfr = nf + (size_t)(b*NV + v)*NF;
        float acc = base;
#pragma unroll
        for (int k = 0; k < NF; k++) acc += nfr[k]*Ws[(NE+k)*NH + t];
        g_nodeenc[(size_t)(b*NV + v)*NH + t] = acc;
    }
}

// ================= wprep + pads fused (+ wcomb split, chunk 7) ===================
extern "C" __global__ void k_pads(const float* __restrict__ bg,
                                  const float* __restrict__ Wh,
                                  const float* __restrict__ W_gat,
                                  const float* __restrict__ b_gat,
                                  const float* __restrict__ a_gat,
                                  const float* __restrict__ W1) {
    int t = threadIdx.x;  // 512
    __shared__ float h1p[128], ghp[384], red[128], h2ps[128];
    for (int i = t; i < 16384; i += 512) {
        int k = i >> 7, c = i & 127;
        float v;
        if (c < 64) v = W1[k*64 + c] + W1[(128+k)*64 + c];
        else        v = W1[(128+k)*64 + (c-64)];
        g_wcomb[i] = v;
    }
    if (t < 128) h1p[t] = (1.f - sigmoidf_(bg[t])) * tanhf(bg[256+t]);
    __syncthreads();
    if (t < 384) {
        float s = 0.f;
#pragma unroll 8
        for (int k = 0; k < 128; k++) s += h1p[k]*Wh[k*384 + t];
        ghp[t] = s;
    } else {
        int c = t - 384;
        float s = b_gat[c];
#pragma unroll 8
        for (int k = 0; k < 128; k++) s += h1p[k]*W_gat[k*128 + c];
        float t2 = tanhf(s);
        g_tpad[c] = t2;
        red[c] = t2*a_gat[c];
    }
    __syncthreads();
    for (int st = 64; st > 0; st >>= 1) { if (t < st) red[t] += red[t+st]; __syncthreads(); }
    if (t == 0) g_lpad[0] = red[0];
    if (t < 128) {
        float z = sigmoidf_(bg[t] + ghp[t]);
        float r = sigmoidf_(bg[128+t] + ghp[128+t]);
        float cand = tanhf(bg[256+t] + r*ghp[256+t]);
        float h2p = z*h1p[t] + (1.f - z)*cand;
        g_h2pad[t] = h2p;
        h2ps[t] = h2p;
        float tb = tanhf(b_gat[t]);
        g_tpad0[t] = tb;
        red[t] = tb*a_gat[t];
    }
    __syncthreads();
    for (int st = 64; st > 0; st >>= 1) { if (t < st) red[t] += red[t+st]; __syncthreads(); }
    if (t == 0) g_lpad0[0] = red[0];
    if (t < 128) {
        float u = 0.f;
#pragma unroll 8
        for (int k = 0; k < 128; k++) u += h2ps[k]*g_wcomb[k*128 + t];
        g_uwpad[t] = u;
    }
    __syncthreads();
    // split wcomb into chunk 7
    for (int i = t; i < 8192; i += 512) {
        int n = i & 127, kp = i >> 7;
        float2 v = make_float2(g_wcomb[(2*kp)*128 + n], g_wcomb[(2*kp+1)*128 + n]);
        uint32_t h, l; splitbf(v, h, l);
        g_wsh[7*8192 + i] = h;
        g_wsl[7*8192 + i] = l;
    }
}

// ================= warp-per-node attention + x ==================================
extern "C" __global__ void k_attn(const int* __restrict__ adj,
                                  const int* __restrict__ num_nodes, int layer) {
    const int tid = threadIdx.x;
    const int lane = tid & 31;
    const int n = blockIdx.x*8 + (tid >> 5);
    const int b = n >> 10;
    const int nn = num_nodes[b];
    const float* tpad = layer ? g_tpad : g_tpad0;
    const float lpadv = (layer ? g_lpad[0] : g_lpad0[0]) - BIGF;

    int adjs = 0; float val = 0.f; float lg = -1e30f;
    if (lane < 16) {
        int a = adj[n*16 + lane];
        val = (a == nn) ? 0.f : 1.f;
        adjs = b*NV + min(a, NV-1);
        lg = (val != 0.f) ? g_lnode[adjs] : lpadv;
    }
    float mx = lg;
#pragma unroll
    for (int o = 16; o; o >>= 1) mx = fmaxf(mx, __shfl_xor_sync(0xffffffffu, mx, o));
    float e = (lane < 16) ? expf(lg - mx) : 0.f;
    float ssum = e;
#pragma unroll
    for (int o = 16; o; o >>= 1) ssum += __shfl_xor_sync(0xffffffffu, ssum, o);
    float at = e / ssum;

    float4 tp4 = *(const float4*)(tpad + lane*4);
    float4 msg = make_float4(0.f, 0.f, 0.f, 0.f);
#pragma unroll
    for (int d = 0; d < 16; d++) {
        float atd = __shfl_sync(0xffffffffu, at, d);
        int   rwd = __shfl_sync(0xffffffffu, adjs, d);
        float vdd = __shfl_sync(0xffffffffu, val, d);
        float4 tv = (vdd != 0.f) ? *(const float4*)(g_tnode + (size_t)rwd*128 + lane*4) : tp4;
        msg.x += atd*tv.x; msg.y += atd*tv.y; msg.z += atd*tv.z; msg.w += atd*tv.w;
    }
    float4 ne = *(const float4*)(g_nodeenc + (size_t)n*128 + lane*4);
    float4 o;
    o.x = tanhf(msg.x + ne.x);
    o.y = tanhf(msg.y + ne.y);
    o.z = tanhf(msg.z + ne.z);
    o.w = tanhf(msg.w + ne.w);
    *(float4*)(g_xnode + (size_t)n*128 + lane*4) = o;
}

// ================= node-level GRU combine (float4) ===============================
extern "C" __global__ void k_combnode(const float* __restrict__ bg, int mode) {
    int idx = blockIdx.x*256 + threadIdx.x;
    int n = idx >> 5;
    int c = (idx & 31)*4;
    const float* hprev = mode ? g_hn1 : g_nodeenc;
    float* out         = mode ? g_hn2 : g_hn1;
    size_t i = (size_t)n*384;
    float4 gxz = *(const float4*)(g_gx + i + c);
    float4 gxr = *(const float4*)(g_gx + i + 128 + c);
    float4 gxc = *(const float4*)(g_gx + i + 256 + c);
    float4 ghz = *(const float4*)(g_gh + i + c);
    float4 ghr = *(const float4*)(g_gh + i + 128 + c);
    float4 ghc = *(const float4*)(g_gh + i + 256 + c);
    float4 hp  = *(const float4*)(hprev + (size_t)n*128 + c);
    float4 bz = *(const float4*)(bg + c);
    float4 br = *(const float4*)(bg + 128 + c);
    float4 bc = *(const float4*)(bg + 256 + c);
    float4 o;
    {
        float z = sigmoidf_(gxz.x + ghz.x + bz.x);
        float r = sigmoidf_(gxr.x + ghr.x + br.x);
        o.x = z*hp.x + (1.f - z)*tanhf(gxc.x + bc.x + r*ghc.x);
    }
    {
        float z = sigmoidf_(gxz.y + ghz.y + bz.y);
        float r = sigmoidf_(gxr.y + ghr.y + br.y);
        o.y = z*hp.y + (1.f - z)*tanhf(gxc.y + bc.y + r*ghc.y);
    }
    {
        float z = sigmoidf_(gxz.z + ghz.z + bz.z);
        float r = sigmoidf_(gxr.z + ghr.z + br.z);
        o.z = z*hp.z + (1.f - z)*tanhf(gxc.z + bc.z + r*ghc.z);
    }
    {
        float z = sigmoidf_(gxz.w + ghz.w + bz.w);
        float r = sigmoidf_(gxr.w + ghr.w + br.w);
        o.w = z*hp.w + (1.f - z)*tanhf(gxc.w + bc.w + r*ghc.w);
    }
    *(float4*)(out + (size_t)n*128 + c) = o;
}

// ================= per-edge nw (float2) ==========================================
extern "C" __global__ void k_nw(const float* __restrict__ b1,
                                const float* __restrict__ W2,
                                const float* __restrict__ b2,
                                const int* __restrict__ adj,
                                const int* __restrict__ num_nodes) {
    int e = blockIdx.x*8 + (threadIdx.x >> 5);
    int lane = threadIdx.x & 31;
    int b = e / VD;
    int d = e & 15;
    int nn = num_nodes[b];
    int a_raw = adj[e];
    int an = min(a_raw, NV-1);
    bool ve = (a_raw != nn);
    int a2_raw = adj[(b*NV + an)*ND + (d ^ 1)];
    int an2 = min(a2_raw, NV-1);
    bool ve2 = (a2_raw != nn);
    const float* rowA = ve  ? (g_uwn + (size_t)(b*NV + an)*NH)        : g_uwpad;
    const float* rowB = ve2 ? (g_uwn + (size_t)(b*NV + an2)*NH + 64)  : (g_uwpad + 64);
    float2 a2 = *(const float2*)(rowA + lane*2);
    float2 c2 = *(const float2*)(rowB + lane*2);
    float2 b12 = *(const float2*)(b1 + lane*2);
    float2 w22 = *(const float2*)(W2 + lane*2);
    float s = tanhf(a2.x + c2.x + b12.x)*w22.x + tanhf(a2.y + c2.y + b12.y)*w22.y;
#pragma unroll
    for (int o = 16; o > 0; o >>= 1) s += __shfl_down_sync(0xffffffff, s, o);
    if (lane == 0) g_nw[e] = s + b2[0];
}

// ================= dual vars (split-K matvec) ====================================
extern "C" __global__ void k_dualvars(const float* __restrict__ W1,
                                      const float* __restrict__ b1,
                                      const float* __restrict__ W2,
                                      const float* __restrict__ b2,
                                      const int* __restrict__ adj,
                                      const int* __restrict__ num_nodes) {
    int bv = blockIdx.x, t = threadIdx.x;  // 128 threads
    int b = bv >> 10;
    __shared__ float ns[128];
    __shared__ float part[128];
    __shared__ float hid[64];
    __shared__ int adjs[16];
    __shared__ float vals[16];
    if (t < 16) {
        int a = adj[bv*16 + t];
        vals[t] = (a == num_nodes[b]) ? 0.f : 1.f;
        adjs[t] = b*NV + min(a, NV-1);
    }
    __syncthreads();
    float hpad = g_h2pad[t];
    float s = 0.f;
#pragma unroll
    for (int d = 0; d < 16; d++)
        s += (vals[d] != 0.f) ? g_hn2[(size_t)adjs[d]*128 + t] : hpad;
    ns[t] = s;
    __syncthreads();
    {
        int j = t & 63;
        int k0 = (t >> 6)*64;
        float a = 0.f;
#pragma unroll 8
        for (int k = 0; k < 64; k++) a += ns[k0+k]*W1[(k0+k)*NHD + j];
        part[t] = a;
    }
    __syncthreads();
    if (t < 64) hid[t] = tanhf(part[t] + part[t+64] + b1[t]) * W2[t];
    __syncthreads();
    for (int st = 32; st > 0; st >>= 1) { if (t < st) hid[t] += hid[t+st]; __syncthreads(); }
    if (t == 0) g_dualvars[bv] = fmaxf(hid[0] + b2[0], 0.f);
}

// ================= fused tail: dest softmax + sparsemax + flow + dual + out ======
#define TAILSM ((3*VD + 1024)*4)
extern "C" __global__ void __launch_bounds__(1024,1)
k_tail(const float* __restrict__ demands, const int* __restrict__ inv_adj,
       const int* __restrict__ adj, const int* __restrict__ num_nodes,
       float* __restrict__ out) {
    extern __shared__ float sm[];
    float* dest_s = sm;
    float* f0  = sm + VD;
    float* f1  = sm + 2*VD;
    float* red = sm + 3*VD;
    const int b = blockIdx.x, v = threadIdx.x;
    const int nn = num_nodes[b];
    const int base = (b*NV + v)*ND;
    const float dem = demands[b*NV + v];

    int ia[16];
    {
        float w[16]; float mx = -1e30f;
#pragma unroll
        for (int d = 0; d < 16; d++) {
            int iar = inv_adj[base + d];
            float m = (iar == nn) ? 1.f : 0.f;
            ia[d] = min(iar, NV-1);
            float val = g_nw[(b*NV + ia[d])*ND + d] - BIGF*m;
            w[d] = val; mx = fmaxf(mx, val);
        }
        float ssum = 0.f;
#pragma unroll
        for (int d = 0; d < 16; d++) { w[d] = expf(w[d]-mx); ssum += w[d]; }
        float inv = 1.f/ssum;
#pragma unroll
        for (int d = 0; d < 16; d++) dest_s[d*NV + v] = w[d]*inv;
    }
    __syncthreads();

    float nrm[16];
    {
        float z[16], valid[16];
#pragma unroll
        for (int d = 0; d < 16; d++) {
            int a = adj[base + d];
            float m = (a == nn) ? 1.f : 0.f;
            valid[d] = 1.f - m;
            z[d] = dest_s[d*NV + min(a, NV-1)] - BIGF*m;
        }
        float zs[16];
        for (int d = 0; d < 16; d++) zs[d] = z[d];
        for (int i = 1; i < 16; i++) {
            float key = zs[i]; int j = i-1;
            while (j >= 0 && zs[j] < key) { zs[j+1] = zs[j]; j--; }
            zs[j+1] = key;
        }
        float csum = 0.f, zck = 0.f; int kz = 1;
        for (int k = 1; k <= 16; k++) {
            csum += zs[k-1];
            if (1.f + (float)k*zs[k-1] > csum) { kz = k; zck = csum; }
        }
        float tau = (zck - 1.f)/(float)kz;
#pragma unroll
        for (int d = 0; d < 16; d++)
            nrm[d] = fmaxf(z[d] - tau, 0.f) * valid[d];
    }

#pragma unroll
    for (int d = 0; d < 16; d++) f0[d*NV + v] = 0.f;
    __syncthreads();
    float* cur = f0; float* nxt = f1;
    for (int it = 0; it < 10; it++) {
        float inflow = 0.f;
#pragma unroll
        for (int d = 0; d < 16; d++) inflow += cur[d*NV + ia[d]];
        float val = fmaxf(inflow - dem, 0.f);
#pragma unroll
        for (int d = 0; d < 16; d++) nxt[d*NV + v] = nrm[d]*val;
        __syncthreads();
        float* tmp = cur; cur = nxt; nxt = tmp;
    }
    float c = 0.f;
#pragma unroll
    for (int d = 0; d < 16; d++) { float f = cur[d*NV + v]; c += f*f; }

    float dvv = g_dualvars[b*NV + v];
    float ddem = dvv*dem;
    float ec = 0.f;
#pragma unroll
    for (int d = 0; d < 16; d++) {
        int a = adj[base + d];
        float m = (a == nn) ? 1.f : 0.f;
        float valid = 1.f - m;
        float dual = m*dvv;
        float dtr = g_dualvars[b*NV + min(a, NV-1)]*valid;
        float dd = dtr - dual;
        float f = 0.f, vel = 0.f;
#pragma unroll
        for (int it = 0; it < 10; it++) {
            float grad = 2.f*f + dd;
            vel = 0.9f*vel - 0.01f*grad;
            f = fmaxf(f + vel, 0.f);
        }
        float df = f*valid;
        ec += df*df + dd*df;
    }
    red[v] = c - ec + ddem;
    __syncthreads();
    for (int s = 512; s > 0; s >>= 1) { if (v < s) red[v] += red[v+s]; __syncthreads(); }
    if (v == 0) out[b] = red[0];
}

extern "C" void kernel_launch(void* const* d_in, const int* in_sizes, int n_in,
                              void* d_out, int out_size) {
    const float* demands       = (const float*)d_in[0];
    const float* node_features = (const float*)d_in[1];
    const float* node_emb      = (const float*)d_in[4];
    const float* W_enc   = (const float*)d_in[5];
    const float* b_enc   = (const float*)d_in[6];
    const float* W_gat   = (const float*)d_in[7];
    const float* b_gat   = (const float*)d_in[8];
    const float* a_gat   = (const float*)d_in[9];
    const float* W_gru_x = (const float*)d_in[10];
    const float* W_gru_h = (const float*)d_in[11];
    const float* b_gru   = (const float*)d_in[12];
    const float* W_dec1  = (const float*)d_in[13];
    const float* b_dec1  = (const float*)d_in[14];
    const float* W_dec2  = (const float*)d_in[15];
    const float* b_dec2  = (const float*)d_in[16];
    const float* W_dual1 = (const float*)d_in[17];
    const float* b_dual1 = (const float*)d_in[18];
    const float* W_dual2 = (const float*)d_in[19];
    const float* b_dual2 = (const float*)d_in[20];
    const int* adj       = (const int*)d_in[21];
    const int* inv_adj   = (const int*)d_in[22];
    const int* num_nodes = (const int*)d_in[26];
    float* out = (float*)d_out;

    cudaFuncSetAttribute(k_tnode, cudaFuncAttributeMaxDynamicSharedMemorySize, TMM_SMEM);
    cudaFuncSetAttribute(k_gh,    cudaFuncAttributeMaxDynamicSharedMemorySize, TMM_SMEM);
    cudaFuncSetAttribute(k_tmm,   cudaFuncAttributeMaxDynamicSharedMemorySize, TMM_SMEM);
    cudaFuncSetAttribute(k_tail,  cudaFuncAttributeMaxDynamicSharedMemorySize, TAILSM);

    dim3 g3(NNODES/64, 3);
    dim3 g1(NNODES/64, 1);

    // fork side stream off the (capturing) main stream
    cudaEventRecord(g_ev[0], 0);
    cudaStreamWaitEvent(g_sB, g_ev[0], 0);

    // main: node encoding ; side: weight pre-split + pads
    k_nodeencF<<<NV, 128>>>(node_emb, node_features, W_enc, b_enc);
    cudaEventRecord(g_ev[1], 0);                                     // nodeenc ready
    k_wsplit<<<7, 256, 0, g_sB>>>(W_gat, W_gru_h, W_gru_x);
    cudaEventRecord(g_ev[8], g_sB);                                  // wsplit ready
    k_pads<<<1, 512, 0, g_sB>>>(b_gru, W_gru_h, W_gat, b_gat, a_gat, W_dec1);
    cudaEventRecord(g_ev[2], g_sB);                                  // pads ready

    // ---- layer 1 ----
    cudaStreamWaitEvent(g_sB, g_ev[1], 0);
    k_gh<<<g3, 256, TMM_SMEM, g_sB>>>(0);                            // side: gh1
    cudaEventRecord(g_ev[3], g_sB);

    cudaStreamWaitEvent(0, g_ev[8], 0);                              // wsplit needed
    k_tnode<<<NNODES/64, 256, TMM_SMEM>>>(b_gat, a_gat, 0);          // main: tnode1
    cudaStreamWaitEvent(0, g_ev[2], 0);                              // pads needed by attn
    k_attn<<<NNODES/8, 256>>>(adj, num_nodes, 0);
    k_tmm<<<g3, 256, TMM_SMEM>>>(2, 0);                              // gx1
    cudaStreamWaitEvent(0, g_ev[3], 0);                              // gh1 needed
    k_combnode<<<NNODES/8, 256>>>(b_gru, 0);                         // -> H1
    cudaEventRecord(g_ev[4], 0);                                     // H1 ready

    // ---- layer 2 ----
    cudaStreamWaitEvent(g_sB, g_ev[4], 0);
    k_gh<<<g3, 256, TMM_SMEM, g_sB>>>(1);                            // side: gh2
    cudaEventRecord(g_ev[5], g_sB);

    k_tnode<<<NNODES/64, 256, TMM_SMEM>>>(b_gat, a_gat, 1);          // main: tnode2
    k_attn<<<NNODES/8, 256>>>(adj, num_nodes, 1);
    k_tmm<<<g3, 256, TMM_SMEM>>>(2, 0);                              // gx2
    cudaStreamWaitEvent(0, g_ev[5], 0);                              // gh2 needed
    k_combnode<<<NNODES/8, 256>>>(b_gru, 1);                         // -> H2
    cudaEventRecord(g_ev[6], 0);                                     // H2 ready

    // ---- tail: dualvars on side stream, decoder chain on main ----
    cudaStreamWaitEvent(g_sB, g_ev[6], 0);
    k_dualvars<<<NNODES, 128, 0, g_sB>>>(W_dual1, b_dual1, W_dual2, b_dual2, adj, num_nodes);
    cudaEventRecord(g_ev[7], g_sB);

    k_tmm<<<g1, 256, TMM_SMEM>>>(3, 3);                              // uwn = H2 @ wcomb
    k_nw<<<ROWS_TOTAL/8, 256>>>(b_dec1, W_dec2, b_dec2, adj, num_nodes);
    cudaStreamWaitEvent(0, g_ev[7], 0);                              // dualvars needed
    k_tail<<<NB, 1024, TAILSM>>>(demands, inv_adj, adj, num_nodes, out);
}

// round 17
// speedup vs baseline: 1.1854x; 1.0117x over previous
#include <cuda_runtime.h>
#include <math.h>
#include <stdint.h>

#define NB 16
#define NV 1024
#define ND 16
#define NE 64
#define NF 16
#define NH 128
#define NHD 64
#define BIGF 1e9f
#define VD (NV*ND)
#define ROWS_TOTAL (NB*VD)
#define NNODES (NB*NV)

// ---- scratch ------------------------------------------------------------------
__device__ float g_nodeenc[NNODES*NH];
__device__ float g_xnode[NNODES*NH];
__device__ float g_tnode[NNODES*NH];
__device__ float g_lnode[NNODES];
__device__ float g_hn1[NNODES*NH];
__device__ float g_hn2[NNODES*NH];
__device__ float g_gx[NNODES*3*NH];
__device__ float g_gh[NNODES*3*NH];
__device__ float g_uwn[NNODES*NH];
__device__ float g_wcomb[NH*NH];
__device__ float g_tpad0[NH];
__device__ float g_lpad0[1];
__device__ float g_tpad[NH];
__device__ float g_lpad[1];
__device__ float g_h2pad[NH];
__device__ float g_uwpad[NH];
__device__ float g_nw[ROWS_TOTAL];
__device__ float g_dualvars[NNODES];
__device__ float g_dualpart[NNODES];
// pre-split weight panels: chunk 0=Wgat, 1..3=Wh, 4..6=Wx, 7=wcomb ([kp*128+n])
__device__ uint32_t g_wsh[8*8192];
__device__ uint32_t g_wsl[8*8192];

// ---- host-side stream/events ----------------------------------------------------
static cudaStream_t g_sB;
static cudaEvent_t  g_ev[10];
namespace {
struct StreamInit {
    StreamInit() {
        cudaStreamCreateWithFlags(&g_sB, cudaStreamNonBlocking);
        for (int i = 0; i < 10; i++)
            cudaEventCreateWithFlags(&g_ev[i], cudaEventDisableTiming);
    }
};
static StreamInit s_streamInit;
}

__device__ __forceinline__ float sigmoidf_(float x) { return 1.f/(1.f+expf(-x)); }

// ---- bf16x2-split mma helpers ---------------------------------------------------
__device__ __forceinline__ void splitbf(float2 v, uint32_t &h, uint32_t &l) {
    asm("cvt.rn.bf16x2.f32 %0, %1, %2;" : "=r"(h) : "f"(v.y), "f"(v.x));
    float hx = __uint_as_float(h << 16);
    float hy = __uint_as_float(h & 0xffff0000u);
    asm("cvt.rn.bf16x2.f32 %0, %1, %2;" : "=r"(l) : "f"(v.y - hy), "f"(v.x - hx));
}
__device__ __forceinline__ void mma_bf16(float (&c)[4],
                                         uint32_t a0, uint32_t a1, uint32_t a2, uint32_t a3,
                                         uint32_t b0, uint32_t b1) {
    asm volatile("mma.sync.aligned.m16n8k16.row.col.f32.bf16.bf16.f32 "
                 "{%0,%1,%2,%3},{%4,%5,%6,%7},{%8,%9},{%0,%1,%2,%3};"
                 : "+f"(c[0]), "+f"(c[1]), "+f"(c[2]), "+f"(c[3])
                 : "r"(a0), "r"(a1), "r"(a2), "r"(a3), "r"(b0), "r"(b1));
}

// smem (uint32 units):
//   A hi/lo: [64 rows][68]  (row-major k-pairs, stride 68)
//   B hi/lo: [64 kp][136]   (k-major, stride 136 -> conflict-free ld+st)
#define AH_OFF 0
#define AL_OFF (64*68)
#define BH_OFF (2*64*68)
#define BL_OFF (2*64*68 + 64*136)
#define RED_OFF (2*64*68 + 2*64*136)
#define TMM_SMEM ((2*64*68 + 2*64*136 + 256)*4)

// stage A tile (64 rows x 128 k): float4 loads, split, uint2 stores
__device__ __forceinline__ void stageA(uint32_t* sm_u, const float* __restrict__ A,
                                       int r0, int tid) {
    for (int i = tid; i < 2048; i += 256) {
        int idx = i*2;                 // pair index (even)
        int r = idx >> 6, p = idx & 63;
        float4 v = *(const float4*)(A + (size_t)(r0+r)*128 + p*2);
        uint32_t h0, l0, h1, l1;
        splitbf(make_float2(v.x, v.y), h0, l0);
        splitbf(make_float2(v.z, v.w), h1, l1);
        *(uint2*)(sm_u + AH_OFF + r*68 + p) = make_uint2(h0, h1);
        *(uint2*)(sm_u + AL_OFF + r*68 + p) = make_uint2(l0, l1);
    }
}
// stage B tile from pre-split global: pure uint4 copy
__device__ __forceinline__ void stageB(uint32_t* sm_u, int chunk, int tid) {
    const uint32_t* wh = g_wsh + chunk*8192;
    const uint32_t* wl = g_wsl + chunk*8192;
    for (int i = tid; i < 2048; i += 256) {
        int idx = i*4;
        int n = idx & 127, kp = idx >> 7;
        *(uint4*)(sm_u + BH_OFF + kp*136 + n) = *(const uint4*)(wh + idx);
        *(uint4*)(sm_u + BL_OFF + kp*136 + n) = *(const uint4*)(wl + idx);
    }
}

// GEMM mainloop on pre-split tiles: pure LDS + MMA
__device__ __forceinline__ void tmm_core(const uint32_t* __restrict__ sm_u,
                                         float (&c)[2][4][4],
                                         int wm, int wn, int g, int t4) {
#pragma unroll
    for (int ks = 0; ks < 8; ks++) {
        const int ka = ks*8 + t4;
        uint32_t ah[2][4], al[2][4];
#pragma unroll
        for (int mt = 0; mt < 2; mt++) {
            int rb = wm*32 + mt*16 + g;
            ah[mt][0] = sm_u[AH_OFF + rb*68 + ka];
            ah[mt][1] = sm_u[AH_OFF + (rb+8)*68 + ka];
            ah[mt][2] = sm_u[AH_OFF + rb*68 + ka + 4];
            ah[mt][3] = sm_u[AH_OFF + (rb+8)*68 + ka + 4];
            al[mt][0] = sm_u[AL_OFF + rb*68 + ka];
            al[mt][1] = sm_u[AL_OFF + (rb+8)*68 + ka];
            al[mt][2] = sm_u[AL_OFF + rb*68 + ka + 4];
            al[mt][3] = sm_u[AL_OFF + (rb+8)*68 + ka + 4];
        }
        uint32_t bh[4][2], bl[4][2];
#pragma unroll
        for (int nt = 0; nt < 4; nt++) {
            int cb = wn*32 + nt*8 + g;
            bh[nt][0] = sm_u[BH_OFF + ka*136 + cb];
            bh[nt][1] = sm_u[BH_OFF + (ka+4)*136 + cb];
            bl[nt][0] = sm_u[BL_OFF + ka*136 + cb];
            bl[nt][1] = sm_u[BL_OFF + (ka+4)*136 + cb];
        }
#pragma unroll
        for (int mt = 0; mt < 2; mt++)
#pragma unroll
            for (int nt = 0; nt < 4; nt++) {
                mma_bf16(c[mt][nt], ah[mt][0],ah[mt][1],ah[mt][2],ah[mt][3], bh[nt][0],bh[nt][1]);
                mma_bf16(c[mt][nt], ah[mt][0],ah[mt][1],ah[mt][2],ah[mt][3], bl[nt][0],bl[nt][1]);
                mma_bf16(c[mt][nt], al[mt][0],al[mt][1],al[mt][2],al[mt][3], bh[nt][0],bh[nt][1]);
            }
    }
}

// ================= k_wsplit: pre-split weight panels 0..6 ========================
extern "C" __global__ void k_wsplit(const float* __restrict__ Wgat,
                                    const float* __restrict__ Wh,
                                    const float* __restrict__ Wx) {
    const int chunk = blockIdx.x;    // 0..6
    const float* W;
    int ws, colBase;
    if (chunk == 0)      { W = Wgat; ws = 128; colBase = 0; }
    else if (chunk < 4)  { W = Wh;   ws = 384; colBase = (chunk-1)*128; }
    else                 { W = Wx;   ws = 384; colBase = (chunk-4)*128; }
    for (int i = threadIdx.x; i < 8192; i += 256) {
        int n = i & 127, kp = i >> 7;
        float2 v = make_float2(W[(2*kp)*ws + colBase + n], W[(2*kp+1)*ws + colBase + n]);
        uint32_t h, l; splitbf(v, h, l);
        g_wsh[chunk*8192 + i] = h;
        g_wsl[chunk*8192 + i] = l;
    }
}

// ================= k_tnode: tnode/lnode GEMM (chunk 0) ===========================
extern "C" __global__ void __launch_bounds__(256,2)
k_tnode(const float* __restrict__ b_gat, const float* __restrict__ a_gat, int asel) {
    extern __shared__ uint32_t sm_u[];
    float* red = (float*)(sm_u + RED_OFF);
    const float* A = asel ? g_hn1 : g_nodeenc;
    const int r0 = blockIdx.x * 64;
    const int tid = threadIdx.x;

    stageA(sm_u, A, r0, tid);
    stageB(sm_u, 0, tid);
    __syncthreads();

    const int warp = tid >> 5, lane = tid & 31;
    const int wm = warp & 1, wn = warp >> 1;
    const int g = lane >> 2, t4 = lane & 3;

    float c[2][4][4];
#pragma unroll
    for (int mt = 0; mt < 2; mt++)
#pragma unroll
        for (int nt = 0; nt < 4; nt++) {
            int col = wn*32 + nt*8 + 2*t4;
            c[mt][nt][0] = b_gat[col];  c[mt][nt][1] = b_gat[col+1];
            c[mt][nt][2] = b_gat[col];  c[mt][nt][3] = b_gat[col+1];
        }
    tmm_core(sm_u, c, wm, wn, g, t4);

#pragma unroll
    for (int mt = 0; mt < 2; mt++) {
        int rA = wm*32 + mt*16 + g;
        float lsA = 0.f, lsB = 0.f;
#pragma unroll
        for (int nt = 0; nt < 4; nt++) {
            int col = wn*32 + nt*8 + 2*t4;
            float t0 = tanhf(c[mt][nt][0]);
            float t1 = tanhf(c[mt][nt][1]);
            float t2 = tanhf(c[mt][nt][2]);
            float t3 = tanhf(c[mt][nt][3]);
            *(float2*)(g_tnode + (size_t)(r0+rA  )*128 + col) = make_float2(t0,t1);
            *(float2*)(g_tnode + (size_t)(r0+rA+8)*128 + col) = make_float2(t2,t3);
            float a0v = a_gat[col], a1v = a_gat[col+1];
            lsA += t0*a0v + t1*a1v;
            lsB += t2*a0v + t3*a1v;
        }
#pragma unroll
        for (int o = 1; o < 4; o <<= 1) {
            lsA += __shfl_xor_sync(0xffffffff, lsA, o);
            lsB += __shfl_xor_sync(0xffffffff, lsB, o);
        }
        if (t4 == 0) {
            red[rA*4 + wn]     = lsA;
            red[(rA+8)*4 + wn] = lsB;
        }
    }
    __syncthreads();
    if (tid < 64) {
        float l = red[tid*4] + red[tid*4+1] + red[tid*4+2] + red[tid*4+3];
        g_lnode[r0 + tid] = l;
    }
}

// ================= k_gh: gh chunks (grid (NNODES/64, 3), chunk 1+y) ==============
extern "C" __global__ void __launch_bounds__(256,2)
k_gh(int asel) {
    extern __shared__ uint32_t sm_u[];
    const float* A = asel ? g_hn1 : g_nodeenc;
    const int y  = blockIdx.y;
    const int r0 = blockIdx.x * 64;
    const int tid = threadIdx.x;

    stageA(sm_u, A, r0, tid);
    stageB(sm_u, 1 + y, tid);
    __syncthreads();

    const int warp = tid >> 5, lane = tid & 31;
    const int wm = warp & 1, wn = warp >> 1;
    const int g = lane >> 2, t4 = lane & 3;

    float c[2][4][4];
#pragma unroll
    for (int mt = 0; mt < 2; mt++)
#pragma unroll
        for (int nt = 0; nt < 4; nt++)
            c[mt][nt][0]=c[mt][nt][1]=c[mt][nt][2]=c[mt][nt][3]=0.f;
    tmm_core(sm_u, c, wm, wn, g, t4);

#pragma unroll
    for (int mt = 0; mt < 2; mt++) {
        int rA = r0 + wm*32 + mt*16 + g;
#pragma unroll
        for (int nt = 0; nt < 4; nt++) {
            int col = y*128 + wn*32 + nt*8 + 2*t4;
            *(float2*)(g_gh + (size_t)rA*384 + col)     = make_float2(c[mt][nt][0], c[mt][nt][1]);
            *(float2*)(g_gh + (size_t)(rA+8)*384 + col) = make_float2(c[mt][nt][2], c[mt][nt][3]);
        }
    }
}

// ================= k_tmm: osel 0 = gx (chunk 4+y), osel 3 = udec (chunk 7) =======
extern "C" __global__ void __launch_bounds__(256,2)
k_tmm(int asel, int osel) {
    extern __shared__ uint32_t sm_u[];
    const float* A = (asel==2) ? g_xnode : g_hn2;
    const int chunk = (osel==3) ? 7 : (4 + blockIdx.y);
    const int colBase = blockIdx.y * 128;
    const int r0 = blockIdx.x * 64;
    const int tid = threadIdx.x;

    stageA(sm_u, A, r0, tid);
    stageB(sm_u, chunk, tid);
    __syncthreads();

    const int warp = tid >> 5, lane = tid & 31;
    const int wm = warp & 1, wn = warp >> 1;
    const int g = lane >> 2, t4 = lane & 3;

    float c[2][4][4];
#pragma unroll
    for (int mt = 0; mt < 2; mt++)
#pragma unroll
        for (int nt = 0; nt < 4; nt++)
            c[mt][nt][0]=c[mt][nt][1]=c[mt][nt][2]=c[mt][nt][3]=0.f;
    tmm_core(sm_u, c, wm, wn, g, t4);

    float* out = (osel==0) ? g_gx : g_uwn;
    const int ostride = (osel==0) ? 384 : 128;
#pragma unroll
    for (int mt = 0; mt < 2; mt++) {
        int rA = r0 + wm*32 + mt*16 + g;
#pragma unroll
        for (int nt = 0; nt < 4; nt++) {
            int col = colBase + wn*32 + nt*8 + 2*t4;
            *(float2*)(out + (size_t)rA*ostride + col)     = make_float2(c[mt][nt][0], c[mt][nt][1]);
            *(float2*)(out + (size_t)(rA+8)*ostride + col) = make_float2(c[mt][nt][2], c[mt][nt][3]);
        }
    }
}

// ================= encoding: one block per v, 16 batches, W_enc in smem =========
extern "C" __global__ void __launch_bounds__(128)
k_nodeencF(const float* __restrict__ emb,
           const float* __restrict__ nf,
           const float* __restrict__ W_enc,
           const float* __restrict__ b_enc) {
    const int v = blockIdx.x, t = threadIdx.x;
    __shared__ float Ws[(NE+NF)*NH];
    __shared__ float e_s[NE];
    __shared__ float red[128];
    for (int i = t; i < (NE+NF)*NH; i += 128) Ws[i] = W_enc[i];
    if (t < NE) e_s[t] = emb[v*NE + t];
    __syncthreads();
    red[t] = (t < NE) ? e_s[t]*e_s[t] : 0.f;
    __syncthreads();
    for (int s = 64; s > 0; s >>= 1) { if (t < s) red[t] += red[t+s]; __syncthreads(); }
    float inv = 1.f / fmaxf(sqrtf(red[0]), 1.f);
    float base = b_enc[t];
#pragma unroll 8
    for (int k = 0; k < NE; k++) base += e_s[k]*inv*Ws[k*NH + t];
#pragma unroll
    for (int b = 0; b < NB; b++) {
        const float* nfr = nf + (size_t)(b*NV + v)*NF;
        float acc = base;
#pragma unroll
        for (int k = 0; k < NF; k++) acc += nfr[k]*Ws[(NE+k)*NH + t];
        g_nodeenc[(size_t)(b*NV + v)*NH + t] = acc;
    }
}

// ================= wprep + pads fused (+ wcomb split, chunk 7) ===================
extern "C" __global__ void k_pads(const float* __restrict__ bg,
                                  const float* __restrict__ Wh,
                                  const float* __restrict__ W_gat,
                                  const float* __restrict__ b_gat,
                                  const float* __restrict__ a_gat,
                                  const float* __restrict__ W1) {
    int t = threadIdx.x;  // 512
    __shared__ float h1p[128], ghp[384], red[128], h2ps[128];
    for (int i = t; i < 16384; i += 512) {
        int k = i >> 7, c = i & 127;
        float v;
        if (c < 64) v = W1[k*64 + c] + W1[(128+k)*64 + c];
        else        v = W1[(128+k)*64 + (c-64)];
        g_wcomb[i] = v;
    }
    if (t < 128) h1p[t] = (1.f - sigmoidf_(bg[t])) * tanhf(bg[256+t]);
    __syncthreads();
    if (t < 384) {
        float s = 0.f;
#pragma unroll 8
        for (int k = 0; k < 128; k++) s += h1p[k]*Wh[k*384 + t];
        ghp[t] = s;
    } else {
        int c = t - 384;
        float s = b_gat[c];
#pragma unroll 8
        for (int k = 0; k < 128; k++) s += h1p[k]*W_gat[k*128 + c];
        float t2 = tanhf(s);
        g_tpad[c] = t2;
        red[c] = t2*a_gat[c];
    }
    __syncthreads();
    for (int st = 64; st > 0; st >>= 1) { if (t < st) red[t] += red[t+st]; __syncthreads(); }
    if (t == 0) g_lpad[0] = red[0];
    if (t < 128) {
        float z = sigmoidf_(bg[t] + ghp[t]);
        float r = sigmoidf_(bg[128+t] + ghp[128+t]);
        float cand = tanhf(bg[256+t] + r*ghp[256+t]);
        float h2p = z*h1p[t] + (1.f - z)*cand;
        g_h2pad[t] = h2p;
        h2ps[t] = h2p;
        float tb = tanhf(b_gat[t]);
        g_tpad0[t] = tb;
        red[t] = tb*a_gat[t];
    }
    __syncthreads();
    for (int st = 64; st > 0; st >>= 1) { if (t < st) red[t] += red[t+st]; __syncthreads(); }
    if (t == 0) g_lpad0[0] = red[0];
    if (t < 128) {
        float u = 0.f;
#pragma unroll 8
        for (int k = 0; k < 128; k++) u += h2ps[k]*g_wcomb[k*128 + t];
        g_uwpad[t] = u;
    }
    __syncthreads();
    for (int i = t; i < 8192; i += 512) {
        int n = i & 127, kp = i >> 7;
        float2 v = make_float2(g_wcomb[(2*kp)*128 + n], g_wcomb[(2*kp+1)*128 + n]);
        uint32_t h, l; splitbf(v, h, l);
        g_wsh[7*8192 + i] = h;
        g_wsl[7*8192 + i] = l;
    }
}

// ================= warp-per-node attention + x ==================================
extern "C" __global__ void k_attn(const int* __restrict__ adj,
                                  const int* __restrict__ num_nodes, int layer) {
    const int tid = threadIdx.x;
    const int lane = tid & 31;
    const int n = blockIdx.x*8 + (tid >> 5);
    const int b = n >> 10;
    const int nn = num_nodes[b];
    const float* tpad = layer ? g_tpad : g_tpad0;
    const float lpadv = (layer ? g_lpad[0] : g_lpad0[0]) - BIGF;

    int adjs = 0; float val = 0.f; float lg = -1e30f;
    if (lane < 16) {
        int a = adj[n*16 + lane];
        val = (a == nn) ? 0.f : 1.f;
        adjs = b*NV + min(a, NV-1);
        lg = (val != 0.f) ? g_lnode[adjs] : lpadv;
    }
    float mx = lg;
#pragma unroll
    for (int o = 16; o; o >>= 1) mx = fmaxf(mx, __shfl_xor_sync(0xffffffffu, mx, o));
    float e = (lane < 16) ? expf(lg - mx) : 0.f;
    float ssum = e;
#pragma unroll
    for (int o = 16; o; o >>= 1) ssum += __shfl_xor_sync(0xffffffffu, ssum, o);
    float at = e / ssum;

    float4 tp4 = *(const float4*)(tpad + lane*4);
    float4 msg = make_float4(0.f, 0.f, 0.f, 0.f);
#pragma unroll
    for (int d = 0; d < 16; d++) {
        float atd = __shfl_sync(0xffffffffu, at, d);
        int   rwd = __shfl_sync(0xffffffffu, adjs, d);
        float vdd = __shfl_sync(0xffffffffu, val, d);
        float4 tv = (vdd != 0.f) ? *(const float4*)(g_tnode + (size_t)rwd*128 + lane*4) : tp4;
        msg.x += atd*tv.x; msg.y += atd*tv.y; msg.z += atd*tv.z; msg.w += atd*tv.w;
    }
    float4 ne = *(const float4*)(g_nodeenc + (size_t)n*128 + lane*4);
    float4 o;
    o.x = tanhf(msg.x + ne.x);
    o.y = tanhf(msg.y + ne.y);
    o.z = tanhf(msg.z + ne.z);
    o.w = tanhf(msg.w + ne.w);
    *(float4*)(g_xnode + (size_t)n*128 + lane*4) = o;
}

// ================= node-level GRU combine (float4) ===============================
extern "C" __global__ void k_combnode(const float* __restrict__ bg, int mode) {
    int idx = blockIdx.x*256 + threadIdx.x;
    int n = idx >> 5;
    int c = (idx & 31)*4;
    const float* hprev = mode ? g_hn1 : g_nodeenc;
    float* out         = mode ? g_hn2 : g_hn1;
    size_t i = (size_t)n*384;
    float4 gxz = *(const float4*)(g_gx + i + c);
    float4 gxr = *(const float4*)(g_gx + i + 128 + c);
    float4 gxc = *(const float4*)(g_gx + i + 256 + c);
    float4 ghz = *(const float4*)(g_gh + i + c);
    float4 ghr = *(const float4*)(g_gh + i + 128 + c);
    float4 ghc = *(const float4*)(g_gh + i + 256 + c);
    float4 hp  = *(const float4*)(hprev + (size_t)n*128 + c);
    float4 bz = *(const float4*)(bg + c);
    float4 br = *(const float4*)(bg + 128 + c);
    float4 bc = *(const float4*)(bg + 256 + c);
    float4 o;
    {
        float z = sigmoidf_(gxz.x + ghz.x + bz.x);
        float r = sigmoidf_(gxr.x + ghr.x + br.x);
        o.x = z*hp.x + (1.f - z)*tanhf(gxc.x + bc.x + r*ghc.x);
    }
    {
        float z = sigmoidf_(gxz.y + ghz.y + bz.y);
        float r = sigmoidf_(gxr.y + ghr.y + br.y);
        o.y = z*hp.y + (1.f - z)*tanhf(gxc.y + bc.y + r*ghc.y);
    }
    {
        float z = sigmoidf_(gxz.z + ghz.z + bz.z);
        float r = sigmoidf_(gxr.z + ghr.z + br.z);
        o.z = z*hp.z + (1.f - z)*tanhf(gxc.z + bc.z + r*ghc.z);
    }
    {
        float z = sigmoidf_(gxz.w + ghz.w + bz.w);
        float r = sigmoidf_(gxr.w + ghr.w + br.w);
        o.w = z*hp.w + (1.f - z)*tanhf(gxc.w + bc.w + r*ghc.w);
    }
    *(float4*)(out + (size_t)n*128 + c) = o;
}

// ================= per-edge nw (float2) ==========================================
extern "C" __global__ void k_nw(const float* __restrict__ b1,
                                const float* __restrict__ W2,
                                const float* __restrict__ b2,
                                const int* __restrict__ adj,
                                const int* __restrict__ num_nodes) {
    int e = blockIdx.x*8 + (threadIdx.x >> 5);
    int lane = threadIdx.x & 31;
    int b = e / VD;
    int d = e & 15;
    int nn = num_nodes[b];
    int a_raw = adj[e];
    int an = min(a_raw, NV-1);
    bool ve = (a_raw != nn);
    int a2_raw = adj[(b*NV + an)*ND + (d ^ 1)];
    int an2 = min(a2_raw, NV-1);
    bool ve2 = (a2_raw != nn);
    const float* rowA = ve  ? (g_uwn + (size_t)(b*NV + an)*NH)        : g_uwpad;
    const float* rowB = ve2 ? (g_uwn + (size_t)(b*NV + an2)*NH + 64)  : (g_uwpad + 64);
    float2 a2 = *(const float2*)(rowA + lane*2);
    float2 c2 = *(const float2*)(rowB + lane*2);
    float2 b12 = *(const float2*)(b1 + lane*2);
    float2 w22 = *(const float2*)(W2 + lane*2);
    float s = tanhf(a2.x + c2.x + b12.x)*w22.x + tanhf(a2.y + c2.y + b12.y)*w22.y;
#pragma unroll
    for (int o = 16; o > 0; o >>= 1) s += __shfl_down_sync(0xffffffff, s, o);
    if (lane == 0) g_nw[e] = s + b2[0];
}

// ================= dual vars (split-K matvec) ====================================
extern "C" __global__ void k_dualvars(const float* __restrict__ W1,
                                      const float* __restrict__ b1,
                                      const float* __restrict__ W2,
                                      const float* __restrict__ b2,
                                      const int* __restrict__ adj,
                                      const int* __restrict__ num_nodes) {
    int bv = blockIdx.x, t = threadIdx.x;  // 128 threads
    int b = bv >> 10;
    __shared__ float ns[128];
    __shared__ float part[128];
    __shared__ float hid[64];
    __shared__ int adjs[16];
    __shared__ float vals[16];
    if (t < 16) {
        int a = adj[bv*16 + t];
        vals[t] = (a == num_nodes[b]) ? 0.f : 1.f;
        adjs[t] = b*NV + min(a, NV-1);
    }
    __syncthreads();
    float hpad = g_h2pad[t];
    float s = 0.f;
#pragma unroll
    for (int d = 0; d < 16; d++)
        s += (vals[d] != 0.f) ? g_hn2[(size_t)adjs[d]*128 + t] : hpad;
    ns[t] = s;
    __syncthreads();
    {
        int j = t & 63;
        int k0 = (t >> 6)*64;
        float a = 0.f;
#pragma unroll 8
        for (int k = 0; k < 64; k++) a += ns[k0+k]*W1[(k0+k)*NHD + j];
        part[t] = a;
    }
    __syncthreads();
    if (t < 64) hid[t] = tanhf(part[t] + part[t+64] + b1[t]) * W2[t];
    __syncthreads();
    for (int st = 32; st > 0; st >>= 1) { if (t < st) hid[t] += hid[t+st]; __syncthreads(); }
    if (t == 0) g_dualvars[bv] = fmaxf(hid[0] + b2[0], 0.f);
}

// ================= dual flows: warp per node, writes g_dualpart ==================
extern "C" __global__ void k_dualflow(const float* __restrict__ demands,
                                      const int* __restrict__ adj,
                                      const int* __restrict__ num_nodes) {
    const int lane = threadIdx.x & 31;
    const int n = blockIdx.x*8 + (threadIdx.x >> 5);   // global node b*NV+v
    const int b = n >> 10;
    const int nn = num_nodes[b];
    const float dvv = g_dualvars[n];

    float ec = 0.f;
    if (lane < 16) {
        int a = adj[n*16 + lane];
        float m = (a == nn) ? 1.f : 0.f;
        float valid = 1.f - m;
        float dual = m*dvv;
        float dtr = g_dualvars[b*NV + min(a, NV-1)]*valid;
        float dd = dtr - dual;
        float f = 0.f, vel = 0.f;
#pragma unroll
        for (int it = 0; it < 10; it++) {
            float grad = 2.f*f + dd;
            vel = 0.9f*vel - 0.01f*grad;
            f = fmaxf(f + vel, 0.f);
        }
        float df = f*valid;
        ec = df*df + dd*df;
    }
#pragma unroll
    for (int o = 16; o; o >>= 1) ec += __shfl_xor_sync(0xffffffffu, ec, o);
    if (lane == 0) g_dualpart[n] = ec - dvv*demands[n];
}

// ================= tail: dest softmax + sparsemax + flow + out ===================
#define TAILSM ((3*VD + 1024)*4)
extern "C" __global__ void __launch_bounds__(1024,1)
k_tail(const float* __restrict__ demands, const int* __restrict__ inv_adj,
       const int* __restrict__ adj, const int* __restrict__ num_nodes,
       float* __restrict__ out) {
    extern __shared__ float sm[];
    float* dest_s = sm;
    float* f0  = sm + VD;
    float* f1  = sm + 2*VD;
    float* red = sm + 3*VD;
    const int b = blockIdx.x, v = threadIdx.x;
    const int nn = num_nodes[b];
    const int base = (b*NV + v)*ND;
    const float dem = demands[b*NV + v];

    int ia[16];
    {
        float w[16]; float mx = -1e30f;
#pragma unroll
        for (int d = 0; d < 16; d++) {
            int iar = inv_adj[base + d];
            float m = (iar == nn) ? 1.f : 0.f;
            ia[d] = min(iar, NV-1);
            float val = g_nw[(b*NV + ia[d])*ND + d] - BIGF*m;
            w[d] = val; mx = fmaxf(mx, val);
        }
        float ssum = 0.f;
#pragma unroll
        for (int d = 0; d < 16; d++) { w[d] = expf(w[d]-mx); ssum += w[d]; }
        float inv = 1.f/ssum;
#pragma unroll
        for (int d = 0; d < 16; d++) dest_s[d*NV + v] = w[d]*inv;
    }
    __syncthreads();

    float nrm[16];
    {
        float z[16], valid[16];
#pragma unroll
        for (int d = 0; d < 16; d++) {
            int a = adj[base + d];
            float m = (a == nn) ? 1.f : 0.f;
            valid[d] = 1.f - m;
            z[d] = dest_s[d*NV + min(a, NV-1)] - BIGF*m;
        }
        float zs[16];
        for (int d = 0; d < 16; d++) zs[d] = z[d];
        for (int i = 1; i < 16; i++) {
            float key = zs[i]; int j = i-1;
            while (j >= 0 && zs[j] < key) { zs[j+1] = zs[j]; j--; }
            zs[j+1] = key;
        }
        float csum = 0.f, zck = 0.f; int kz = 1;
        for (int k = 1; k <= 16; k++) {
            csum += zs[k-1];
            if (1.f + (float)k*zs[k-1] > csum) { kz = k; zck = csum; }
        }
        float tau = (zck - 1.f)/(float)kz;
#pragma unroll
        for (int d = 0; d < 16; d++)
            nrm[d] = fmaxf(z[d] - tau, 0.f) * valid[d];
    }

#pragma unroll
    for (int d = 0; d < 16; d++) f0[d*NV + v] = 0.f;
    __syncthreads();
    float* cur = f0; float* nxt = f1;
    for (int it = 0; it < 10; it++) {
        float inflow = 0.f;
#pragma unroll
        for (int d = 0; d < 16; d++) inflow += cur[d*NV + ia[d]];
        float val = fmaxf(inflow - dem, 0.f);
#pragma unroll
        for (int d = 0; d < 16; d++) nxt[d*NV + v] = nrm[d]*val;
        __syncthreads();
        float* tmp = cur; cur = nxt; nxt = tmp;
    }
    float c = 0.f;
#pragma unroll
    for (int d = 0; d < 16; d++) { float f = cur[d*NV + v]; c += f*f; }

    red[v] = c - g_dualpart[b*NV + v];
    __syncthreads();
    for (int s = 512; s > 0; s >>= 1) { if (v < s) red[v] += red[v+s]; __syncthreads(); }
    if (v == 0) out[b] = red[0];
}

extern "C" void kernel_launch(void* const* d_in, const int* in_sizes, int n_in,
                              void* d_out, int out_size) {
    const float* demands       = (const float*)d_in[0];
    const float* node_features = (const float*)d_in[1];
    const float* node_emb      = (const float*)d_in[4];
    const float* W_enc   = (const float*)d_in[5];
    const float* b_enc   = (const float*)d_in[6];
    const float* W_gat   = (const float*)d_in[7];
    const float* b_gat   = (const float*)d_in[8];
    const float* a_gat   = (const float*)d_in[9];
    const float* W_gru_x = (const float*)d_in[10];
    const float* W_gru_h = (const float*)d_in[11];
    const float* b_gru   = (const float*)d_in[12];
    const float* W_dec1  = (const float*)d_in[13];
    const float* b_dec1  = (const float*)d_in[14];
    const float* W_dec2  = (const float*)d_in[15];
    const float* b_dec2  = (const float*)d_in[16];
    const float* W_dual1 = (const float*)d_in[17];
    const float* b_dual1 = (const float*)d_in[18];
    const float* W_dual2 = (const float*)d_in[19];
    const float* b_dual2 = (const float*)d_in[20];
    const int* adj       = (const int*)d_in[21];
    const int* inv_adj   = (const int*)d_in[22];
    const int* num_nodes = (const int*)d_in[26];
    float* out = (float*)d_out;

    cudaFuncSetAttribute(k_tnode, cudaFuncAttributeMaxDynamicSharedMemorySize, TMM_SMEM);
    cudaFuncSetAttribute(k_gh,    cudaFuncAttributeMaxDynamicSharedMemorySize, TMM_SMEM);
    cudaFuncSetAttribute(k_tmm,   cudaFuncAttributeMaxDynamicSharedMemorySize, TMM_SMEM);
    cudaFuncSetAttribute(k_tail,  cudaFuncAttributeMaxDynamicSharedMemorySize, TAILSM);

    dim3 g3(NNODES/64, 3);
    dim3 g1(NNODES/64, 1);

    // fork side stream off the (capturing) main stream
    cudaEventRecord(g_ev[0], 0);
    cudaStreamWaitEvent(g_sB, g_ev[0], 0);

    // main: node encoding ; side: weight pre-split + pads
    k_nodeencF<<<NV, 128>>>(node_emb, node_features, W_enc, b_enc);
    cudaEventRecord(g_ev[1], 0);                                     // nodeenc ready
    k_wsplit<<<7, 256, 0, g_sB>>>(W_gat, W_gru_h, W_gru_x);
    cudaEventRecord(g_ev[8], g_sB);                                  // wsplit ready
    k_pads<<<1, 512, 0, g_sB>>>(b_gru, W_gru_h, W_gat, b_gat, a_gat, W_dec1);
    cudaEventRecord(g_ev[2], g_sB);                                  // pads ready

    // ---- layer 1 ----
    cudaStreamWaitEvent(g_sB, g_ev[1], 0);
    k_gh<<<g3, 256, TMM_SMEM, g_sB>>>(0);                            // side: gh1
    cudaEventRecord(g_ev[3], g_sB);

    cudaStreamWaitEvent(0, g_ev[8], 0);                              // wsplit needed
    k_tnode<<<NNODES/64, 256, TMM_SMEM>>>(b_gat, a_gat, 0);          // main: tnode1
    cudaStreamWaitEvent(0, g_ev[2], 0);                              // pads needed by attn
    k_attn<<<NNODES/8, 256>>>(adj, num_nodes, 0);
    k_tmm<<<g3, 256, TMM_SMEM>>>(2, 0);                              // gx1
    cudaStreamWaitEvent(0, g_ev[3], 0);                              // gh1 needed
    k_combnode<<<NNODES/8, 256>>>(b_gru, 0);                         // -> H1
    cudaEventRecord(g_ev[4], 0);                                     // H1 ready

    // ---- layer 2 ----
    cudaStreamWaitEvent(g_sB, g_ev[4], 0);
    k_gh<<<g3, 256, TMM_SMEM, g_sB>>>(1);                            // side: gh2
    cudaEventRecord(g_ev[5], g_sB);

    k_tnode<<<NNODES/64, 256, TMM_SMEM>>>(b_gat, a_gat, 1);          // main: tnode2
    k_attn<<<NNODES/8, 256>>>(adj, num_nodes, 1);
    k_tmm<<<g3, 256, TMM_SMEM>>>(2, 0);                              // gx2
    cudaStreamWaitEvent(0, g_ev[5], 0);                              // gh2 needed
    k_combnode<<<NNODES/8, 256>>>(b_gru, 1);                         // -> H2
    cudaEventRecord(g_ev[6], 0);                                     // H2 ready

    // ---- tail: dualvars + dualflow on side stream, decoder chain on main ----
    cudaStreamWaitEvent(g_sB, g_ev[6], 0);
    k_dualvars<<<NNODES, 128, 0, g_sB>>>(W_dual1, b_dual1, W_dual2, b_dual2, adj, num_nodes);
    k_dualflow<<<NNODES/8, 256, 0, g_sB>>>(demands, adj, num_nodes);
    cudaEventRecord(g_ev[7], g_sB);

    k_tmm<<<g1, 256, TMM_SMEM>>>(3, 3);                              // uwn = H2 @ wcomb
    k_nw<<<ROWS_TOTAL/8, 256>>>(b_dec1, W_dec2, b_dec2, adj, num_nodes);
    cudaStreamWaitEvent(0, g_ev[7], 0);                              // dualpart needed
    k_tail<<<NB, 1024, TAILSM>>>(demands, inv_adj, adj, num_nodes, out);
}